// round 3
// baseline (speedup 1.0000x reference)
#include <cuda_runtime.h>
#include <math.h>

#define B_    8
#define N_    4096
#define CIN_  64
#define COUT_ 128
#define R_    32
#define R3_   32768
#define NG_   8
#define GN_EPS_ 1e-5f

// ---------------- scratch (static device globals; no allocation) -------------
static __device__ float g_grid[B_ * CIN_ * R3_];      //  64 MB voxel grid
static __device__ float g_cnt [B_ * R3_];             //   1 MB voxel counts
static __device__ int   g_vox [B_ * N_];              //  voxel flat index per point
static __device__ float g_nc  [B_ * N_ * 3];          //  normalized coords
static __device__ float g_h1  [B_ * COUT_ * R3_];     // 128 MB
static __device__ float g_h2  [B_ * COUT_ * R3_];     // 128 MB
static __device__ float g_pf  [B_ * COUT_ * N_];      //  16 MB point branch
static __device__ float g_mean[B_ * NG_];
static __device__ float g_rstd[B_ * NG_];

// packed fp32x2 FMA (sm_100+): d += a * b on both lanes
__device__ __forceinline__ void fma2(float2& d, const float2& a, const float2& b) {
    asm("fma.rn.f32x2 %0, %1, %2, %0;"
        : "+l"(reinterpret_cast<unsigned long long&>(d))
        : "l"(reinterpret_cast<const unsigned long long&>(a)),
          "l"(reinterpret_cast<const unsigned long long&>(b)));
}

// ---------------- zero voxel grid + counts ----------------------------------
__global__ void zero_kernel(float* __restrict__ grid, float* __restrict__ cnt) {
    int stride = gridDim.x * blockDim.x;
    int t0 = blockIdx.x * blockDim.x + threadIdx.x;
    for (int i = t0; i < B_ * CIN_ * R3_; i += stride) grid[i] = 0.f;
    for (int i = t0; i < B_ * R3_; i += stride) cnt[i] = 0.f;
}

// ---------------- per-batch coord normalization + voxel index + counts ------
__global__ void coords_kernel(const float* __restrict__ coords,
                              float* __restrict__ nc, int* __restrict__ vox,
                              float* __restrict__ cnt) {
    int b = blockIdx.x, tid = threadIdx.x;
    __shared__ float red[256];
    __shared__ float smean[3];
    __shared__ float sinv;

    float s0 = 0.f, s1 = 0.f, s2 = 0.f;
    for (int n = tid; n < N_; n += 256) {
        const float* c = &coords[(b * N_ + n) * 3];
        s0 += c[0]; s1 += c[1]; s2 += c[2];
    }
    float ss[3] = {s0, s1, s2};
    for (int d = 0; d < 3; d++) {
        red[tid] = ss[d]; __syncthreads();
        for (int st = 128; st > 0; st >>= 1) {
            if (tid < st) red[tid] += red[tid + st];
            __syncthreads();
        }
        if (tid == 0) smean[d] = red[0] * (1.0f / N_);
        __syncthreads();
    }
    float m0 = smean[0], m1 = smean[1], m2 = smean[2];

    float mx = 0.f;
    for (int n = tid; n < N_; n += 256) {
        const float* c = &coords[(b * N_ + n) * 3];
        float dx = c[0] - m0, dy = c[1] - m1, dz = c[2] - m2;
        mx = fmaxf(mx, dx * dx + dy * dy + dz * dz);
    }
    red[tid] = mx; __syncthreads();
    for (int st = 128; st > 0; st >>= 1) {
        if (tid < st) red[tid] = fmaxf(red[tid], red[tid + st]);
        __syncthreads();
    }
    if (tid == 0) sinv = 1.0f / (2.0f * sqrtf(red[0]));
    __syncthreads();
    float inv = sinv;

    for (int n = tid; n < N_; n += 256) {
        const float* c = &coords[(b * N_ + n) * 3];
        float v[3]; int iv[3];
        float cc[3] = {c[0] - m0, c[1] - m1, c[2] - m2};
        #pragma unroll
        for (int d = 0; d < 3; d++) {
            float x = (cc[d] * inv + 0.5f) * (float)R_;
            x = fminf(fmaxf(x, 0.f), (float)(R_ - 1));
            v[d] = x;
            iv[d] = (int)rintf(x);
        }
        nc[(b * N_ + n) * 3 + 0] = v[0];
        nc[(b * N_ + n) * 3 + 1] = v[1];
        nc[(b * N_ + n) * 3 + 2] = v[2];
        int flat = (iv[0] * R_ + iv[1]) * R_ + iv[2];
        vox[b * N_ + n] = flat;
        atomicAdd(&cnt[b * R3_ + flat], 1.0f);
    }
}

// ---------------- scatter features into voxel grid --------------------------
__global__ void scatter_kernel(const float* __restrict__ f,
                               const int* __restrict__ vox,
                               float* __restrict__ grid) {
    int t = blockIdx.x * blockDim.x + threadIdx.x;   // over B*CIN*N
    int n = t & (N_ - 1);
    int bc = t >> 12;            // b*CIN + c
    int b = bc >> 6;             // CIN=64
    int flat = vox[b * N_ + n];
    atomicAdd(&grid[bc * R3_ + flat], f[t]);
}

// ---------------- grid /= max(count,1) --------------------------------------
__global__ void normgrid_kernel(float* __restrict__ grid, const float* __restrict__ cnt) {
    int t = blockIdx.x * blockDim.x + threadIdx.x;   // over B*CIN*R3
    int v = t & (R3_ - 1);
    int b = t >> 21;             // / (CIN*R3) = / (64*32768)
    float c = cnt[b * R3_ + v];
    grid[t] = grid[t] / fmaxf(c, 1.0f);
}

// ---------------- 3x3x3 conv, smem-tiled, packed f32x2 FMA ------------------
// block: 256 thr = 16 co x (4x4 xy); each thread computes full z-line as
// 16 float2 accumulators via fma.rn.f32x2 (FFMA2). kz=0/kz=2 taps use the
// naturally aligned LDS.64 pairs; kz=1 needs one register pack per pair.
__global__ __launch_bounds__(256, 3)
void conv3d_kernel(const float* __restrict__ in, const float* __restrict__ w,
                   const float* __restrict__ bias, float* __restrict__ out, int Cin) {
    const int CCH = 4;
    const int ZS = 36;                         // even stride -> 8B-aligned pairs
    __shared__ float sIn[CCH * 6 * 6 * ZS];
    __shared__ float sW[16 * CCH * 27];

    int tid = threadIdx.x;
    int tile = blockIdx.x;
    int co0 = blockIdx.y * 16;
    int b = blockIdx.z;
    int x0 = (tile >> 3) * 4, y0 = (tile & 7) * 4;
    int coL = tid >> 4;
    int co = co0 + coL;
    int lx = (tid & 15) >> 2, ly = tid & 3;

    float2 acc[16];
    float bv = bias[co];
    #pragma unroll
    for (int i = 0; i < 16; i++) acc[i] = make_float2(bv, bv);

    for (int c0 = 0; c0 < Cin; c0 += CCH) {
        // stage input tile (with halo, zero padded)
        for (int t = tid; t < CCH * 6 * 6 * 34; t += 256) {
            int zz = t % 34;
            int r = t / 34;
            int yy = r % 6; r /= 6;
            int xx = r % 6;
            int ci = r / 6;
            int gx = x0 - 1 + xx, gy = y0 - 1 + yy, gz = zz - 1;
            float v = 0.f;
            if ((unsigned)gx < 32u && (unsigned)gy < 32u && (unsigned)gz < 32u)
                v = in[(((b * Cin + c0 + ci) * 32 + gx) * 32 + gy) * 32 + gz];
            sIn[((ci * 6 + xx) * 6 + yy) * ZS + zz] = v;
        }
        // stage weights
        for (int t = tid; t < 16 * CCH * 27; t += 256) {
            int tap = t % 27;
            int r = t / 27;
            int ci = r % CCH;
            int cl = r / CCH;
            sW[t] = w[((co0 + cl) * Cin + c0 + ci) * 27 + tap];
        }
        __syncthreads();

        #pragma unroll 1
        for (int ci = 0; ci < CCH; ci++) {
            #pragma unroll
            for (int kx = 0; kx < 3; kx++) {
                #pragma unroll
                for (int ky = 0; ky < 3; ky++) {
                    const float2* line = (const float2*)&sIn[((ci * 6 + lx + kx) * 6 + (ly + ky)) * ZS];
                    const float* wp = &sW[(coL * CCH + ci) * 27 + (kx * 3 + ky) * 3];
                    float w0 = wp[0], w1 = wp[1], w2 = wp[2];
                    float2 w0d = make_float2(w0, w0);
                    float2 w1d = make_float2(w1, w1);
                    float2 w2d = make_float2(w2, w2);
                    float2 p0 = line[0];
                    #pragma unroll
                    for (int i = 0; i < 16; i++) {
                        float2 p1 = line[i + 1];
                        fma2(acc[i], w0d, p0);             // taps z, z+1 (kz=0)
                        float2 s = make_float2(p0.y, p1.x);
                        fma2(acc[i], w1d, s);              // kz=1 (shifted pair)
                        fma2(acc[i], w2d, p1);             // kz=2
                        p0 = p1;
                    }
                }
            }
        }
        __syncthreads();
    }

    float2* op = (float2*)&out[(((b * COUT_ + co) * 32 + (x0 + lx)) * 32 + (y0 + ly)) * 32];
    #pragma unroll
    for (int i = 0; i < 16; i++) op[i] = acc[i];
}

// ---------------- GroupNorm stats: one block per (b, group) -----------------
__global__ void gn_stats_kernel(const float* __restrict__ x, int S,
                                float* __restrict__ mean, float* __restrict__ rstd) {
    int bg = blockIdx.x;                       // b*8 + g ; group = 16 contiguous ch
    const float* p = x + (long)bg * 16 * S;
    int n = 16 * S;
    float s = 0.f, s2 = 0.f;
    for (int i = threadIdx.x; i < n; i += blockDim.x) {
        float v = p[i];
        s += v; s2 += v * v;
    }
    __shared__ float ra[512], rb[512];
    int tid = threadIdx.x;
    ra[tid] = s; rb[tid] = s2; __syncthreads();
    for (int st = 256; st > 0; st >>= 1) {
        if (tid < st) { ra[tid] += ra[tid + st]; rb[tid] += rb[tid + st]; }
        __syncthreads();
    }
    if (tid == 0) {
        float m = ra[0] / (float)n;
        float var = rb[0] / (float)n - m * m;
        mean[bg] = m;
        rstd[bg] = rsqrtf(var + GN_EPS_);
    }
}

// ---------------- GroupNorm apply + swish (in place) ------------------------
__global__ void gn_apply_kernel(float* __restrict__ x, const float* __restrict__ gamma,
                                const float* __restrict__ beta,
                                const float* __restrict__ mean, const float* __restrict__ rstd,
                                int S) {
    int t = blockIdx.x * blockDim.x + threadIdx.x;   // over B*COUT*S
    int c = (t / S) % COUT_;
    int b = t / (S * COUT_);
    int idx = b * NG_ + (c >> 4);
    float y = (x[t] - mean[idx]) * rstd[idx] * gamma[c] + beta[c];
    x[t] = y / (1.0f + expf(-y));
}

// ---------------- point branch GEMM: pf = pt_w @ features + b ---------------
__global__ void ptgemm_kernel(const float* __restrict__ f, const float* __restrict__ w,
                              const float* __restrict__ bias, float* __restrict__ pf) {
    int t = blockIdx.x * blockDim.x + threadIdx.x;   // over B*(COUT/4)*N
    int n = t & (N_ - 1);
    int r = t >> 12;
    int o = (r & 31) * 4;        // COUT/4 = 32
    int b = r >> 5;
    float a0 = bias[o], a1 = bias[o + 1], a2 = bias[o + 2], a3 = bias[o + 3];
    const float* fb = f + (b * CIN_) * N_ + n;
    const float* w0 = w + o * CIN_;
    #pragma unroll 8
    for (int c = 0; c < CIN_; c++) {
        float fv = fb[c * N_];
        a0 += w0[c] * fv;
        a1 += w0[CIN_ + c] * fv;
        a2 += w0[2 * CIN_ + c] * fv;
        a3 += w0[3 * CIN_ + c] * fv;
    }
    float* op = &pf[(b * COUT_ + o) * N_ + n];
    op[0] = a0; op[N_] = a1; op[2 * N_] = a2; op[3 * N_] = a3;
}

// ---------------- devoxelize + point-branch GN/swish + add ------------------
__global__ void final_kernel(const float* __restrict__ nc, const float* __restrict__ h2,
                             const float* __restrict__ pf, const float* __restrict__ gamma,
                             const float* __restrict__ beta,
                             const float* __restrict__ mean, const float* __restrict__ rstd,
                             float* __restrict__ out) {
    int t = blockIdx.x * blockDim.x + threadIdx.x;   // over B*(COUT/4)*N
    int n = t & (N_ - 1);
    int r = t >> 12;
    int o = (r & 31) * 4;
    int b = r >> 5;

    float ncx = nc[(b * N_ + n) * 3 + 0];
    float ncy = nc[(b * N_ + n) * 3 + 1];
    float ncz = nc[(b * N_ + n) * 3 + 2];
    float fx = floorf(ncx), fy = floorf(ncy), fz = floorf(ncz);
    float dx = ncx - fx, dy = ncy - fy, dz = ncz - fz;
    int ix0 = (int)fx, iy0 = (int)fy, iz0 = (int)fz;
    int ix1 = min(ix0 + 1, R_ - 1), iy1 = min(iy0 + 1, R_ - 1), iz1 = min(iz0 + 1, R_ - 1);
    float wx[2] = {1.f - dx, dx}, wy[2] = {1.f - dy, dy}, wz[2] = {1.f - dz, dz};
    int xs[2] = {ix0, ix1}, ys[2] = {iy0, iy1}, zs[2] = {iz0, iz1};

    float d0 = 0.f, d1 = 0.f, d2 = 0.f, d3 = 0.f;
    const float* hb = &h2[(b * COUT_ + o) * R3_];
    #pragma unroll
    for (int k = 0; k < 8; k++) {
        int kx = k >> 2, ky = (k >> 1) & 1, kz = k & 1;
        float wk = wx[kx] * wy[ky] * wz[kz];
        int id = (xs[kx] * R_ + ys[ky]) * R_ + zs[kz];
        d0 += wk * hb[id];
        d1 += wk * hb[R3_ + id];
        d2 += wk * hb[2 * R3_ + id];
        d3 += wk * hb[3 * R3_ + id];
    }

    int idx = b * NG_ + (o >> 4);        // 4 consecutive ch never cross a group
    float m = mean[idx], rs = rstd[idx];
    const float* pp = &pf[(b * COUT_ + o) * N_ + n];
    float* op = &out[(b * COUT_ + o) * N_ + n];
    float dv[4] = {d0, d1, d2, d3};
    #pragma unroll
    for (int j = 0; j < 4; j++) {
        int c = o + j;
        float y = (pp[j * N_] - m) * rs * gamma[c] + beta[c];
        op[j * N_] = dv[j] + y / (1.0f + expf(-y));
    }
}

// ---------------- host launcher ----------------------------------------------
extern "C" void kernel_launch(void* const* d_in, const int* in_sizes, int n_in,
                              void* d_out, int out_size) {
    const float* features = (const float*)d_in[0];
    const float* coords   = (const float*)d_in[1];
    const float* c1w = (const float*)d_in[2];
    const float* c1b = (const float*)d_in[3];
    const float* g1g = (const float*)d_in[4];
    const float* g1b = (const float*)d_in[5];
    const float* c2w = (const float*)d_in[6];
    const float* c2b = (const float*)d_in[7];
    const float* g2g = (const float*)d_in[8];
    const float* g2b = (const float*)d_in[9];
    const float* ptw = (const float*)d_in[10];
    const float* ptb = (const float*)d_in[11];
    const float* pgg = (const float*)d_in[12];
    const float* pgb = (const float*)d_in[13];
    float* out = (float*)d_out;

    float *grid_p, *cnt_p, *h1, *h2, *pf, *nc, *mean_p, *rstd_p;
    int* vox_p;
    cudaGetSymbolAddress((void**)&grid_p, g_grid);
    cudaGetSymbolAddress((void**)&cnt_p, g_cnt);
    cudaGetSymbolAddress((void**)&vox_p, g_vox);
    cudaGetSymbolAddress((void**)&nc, g_nc);
    cudaGetSymbolAddress((void**)&h1, g_h1);
    cudaGetSymbolAddress((void**)&h2, g_h2);
    cudaGetSymbolAddress((void**)&pf, g_pf);
    cudaGetSymbolAddress((void**)&mean_p, g_mean);
    cudaGetSymbolAddress((void**)&rstd_p, g_rstd);

    zero_kernel<<<4096, 256>>>(grid_p, cnt_p);
    coords_kernel<<<B_, 256>>>(coords, nc, vox_p, cnt_p);
    scatter_kernel<<<8192, 256>>>(features, vox_p, grid_p);          // B*CIN*N
    normgrid_kernel<<<65536, 256>>>(grid_p, cnt_p);                  // B*CIN*R3

    conv3d_kernel<<<dim3(64, 8, 8), 256>>>(grid_p, c1w, c1b, h1, CIN_);
    gn_stats_kernel<<<B_ * NG_, 512>>>(h1, R3_, mean_p, rstd_p);
    gn_apply_kernel<<<131072, 256>>>(h1, g1g, g1b, mean_p, rstd_p, R3_);

    conv3d_kernel<<<dim3(64, 8, 8), 256>>>(h1, c2w, c2b, h2, COUT_);
    gn_stats_kernel<<<B_ * NG_, 512>>>(h2, R3_, mean_p, rstd_p);
    gn_apply_kernel<<<131072, 256>>>(h2, g2g, g2b, mean_p, rstd_p, R3_);

    ptgemm_kernel<<<4096, 256>>>(features, ptw, ptb, pf);            // B*(COUT/4)*N
    gn_stats_kernel<<<B_ * NG_, 512>>>(pf, N_, mean_p, rstd_p);
    final_kernel<<<4096, 256>>>(nc, h2, pf, pgg, pgb, mean_p, rstd_p, out);
}

// round 5
// speedup vs baseline: 3.4677x; 3.4677x over previous
#include <cuda_runtime.h>
#include <cuda_bf16.h>
#include <math.h>
#include <stdint.h>

#define B_    8
#define N_    4096
#define CIN_  64
#define COUT_ 128
#define R_    32
#define R3_   32768
#define NG_   8
#define GN_EPS_ 1e-5f

// ---------------- scratch (static device globals; no allocation) -------------
static __device__ float g_grid[B_ * CIN_ * R3_];
static __device__ float g_cnt [B_ * R3_];
static __device__ int   g_vox [B_ * N_];
static __device__ float g_nc  [B_ * N_ * 3];
static __device__ float g_h1  [B_ * COUT_ * R3_];
static __device__ float g_h2  [B_ * COUT_ * R3_];
static __device__ float g_pf  [B_ * COUT_ * N_];
static __device__ float g_mean[B_ * NG_];
static __device__ float g_rstd[B_ * NG_];
// pre-split weights: [tap][ci-chunk32][co 128][ci 32] bf16, hi/lo planes
static __device__ __nv_bfloat16 g_w1h[27 * 2 * 128 * 32];
static __device__ __nv_bfloat16 g_w1l[27 * 2 * 128 * 32];
static __device__ __nv_bfloat16 g_w2h[27 * 4 * 128 * 32];
static __device__ __nv_bfloat16 g_w2l[27 * 4 * 128 * 32];

// ---------------- mma.sync m16n8k16 bf16 (HMMA path, works on compute_103) ---
#define MMA_B16(dd, a0, a1, a2, a3, b0, b1) \
    asm volatile("mma.sync.aligned.m16n8k16.row.col.f32.bf16.bf16.f32 " \
        "{%0,%1,%2,%3}, {%4,%5,%6,%7}, {%8,%9}, {%0,%1,%2,%3};" \
        : "+f"((dd)[0]), "+f"((dd)[1]), "+f"((dd)[2]), "+f"((dd)[3]) \
        : "r"(a0), "r"(a1), "r"(a2), "r"(a3), "r"(b0), "r"(b1))

// ============================ elementwise kernels ============================
__global__ void zero_kernel(float* __restrict__ grid, float* __restrict__ cnt) {
    int stride = gridDim.x * blockDim.x;
    int t0 = blockIdx.x * blockDim.x + threadIdx.x;
    for (int i = t0; i < B_ * CIN_ * R3_; i += stride) grid[i] = 0.f;
    for (int i = t0; i < B_ * R3_; i += stride) cnt[i] = 0.f;
}

__global__ void coords_kernel(const float* __restrict__ coords,
                              float* __restrict__ nc, int* __restrict__ vox,
                              float* __restrict__ cnt) {
    int b = blockIdx.x, tid = threadIdx.x;
    __shared__ float red[256];
    __shared__ float smean[3];
    __shared__ float sinv;

    float s0 = 0.f, s1 = 0.f, s2 = 0.f;
    for (int n = tid; n < N_; n += 256) {
        const float* c = &coords[(b * N_ + n) * 3];
        s0 += c[0]; s1 += c[1]; s2 += c[2];
    }
    float ss[3] = {s0, s1, s2};
    for (int d = 0; d < 3; d++) {
        red[tid] = ss[d]; __syncthreads();
        for (int st = 128; st > 0; st >>= 1) {
            if (tid < st) red[tid] += red[tid + st];
            __syncthreads();
        }
        if (tid == 0) smean[d] = red[0] * (1.0f / N_);
        __syncthreads();
    }
    float m0 = smean[0], m1 = smean[1], m2 = smean[2];

    float mx = 0.f;
    for (int n = tid; n < N_; n += 256) {
        const float* c = &coords[(b * N_ + n) * 3];
        float dx = c[0] - m0, dy = c[1] - m1, dz = c[2] - m2;
        mx = fmaxf(mx, dx * dx + dy * dy + dz * dz);
    }
    red[tid] = mx; __syncthreads();
    for (int st = 128; st > 0; st >>= 1) {
        if (tid < st) red[tid] = fmaxf(red[tid], red[tid + st]);
        __syncthreads();
    }
    if (tid == 0) sinv = 1.0f / (2.0f * sqrtf(red[0]));
    __syncthreads();
    float inv = sinv;

    for (int n = tid; n < N_; n += 256) {
        const float* c = &coords[(b * N_ + n) * 3];
        float v[3]; int iv[3];
        float cc[3] = {c[0] - m0, c[1] - m1, c[2] - m2};
        #pragma unroll
        for (int d = 0; d < 3; d++) {
            float x = (cc[d] * inv + 0.5f) * (float)R_;
            x = fminf(fmaxf(x, 0.f), (float)(R_ - 1));
            v[d] = x;
            iv[d] = (int)rintf(x);
        }
        nc[(b * N_ + n) * 3 + 0] = v[0];
        nc[(b * N_ + n) * 3 + 1] = v[1];
        nc[(b * N_ + n) * 3 + 2] = v[2];
        int flat = (iv[0] * R_ + iv[1]) * R_ + iv[2];
        vox[b * N_ + n] = flat;
        atomicAdd(&cnt[b * R3_ + flat], 1.0f);
    }
}

__global__ void scatter_kernel(const float* __restrict__ f,
                               const int* __restrict__ vox,
                               float* __restrict__ grid) {
    int t = blockIdx.x * blockDim.x + threadIdx.x;
    int n = t & (N_ - 1);
    int bc = t >> 12;
    int b = bc >> 6;
    int flat = vox[b * N_ + n];
    atomicAdd(&grid[bc * R3_ + flat], f[t]);
}

__global__ void normgrid_kernel(float* __restrict__ grid, const float* __restrict__ cnt) {
    int t = blockIdx.x * blockDim.x + threadIdx.x;
    int v = t & (R3_ - 1);
    int b = t >> 21;
    float c = cnt[b * R3_ + v];
    grid[t] = grid[t] / fmaxf(c, 1.0f);
}

// ---------------- weight prep: fp32 -> bf16 hi/lo, GEMM-friendly layout ------
__global__ void wprep_kernel(const float* __restrict__ w, __nv_bfloat16* __restrict__ hi,
                             __nv_bfloat16* __restrict__ lo, int Cin) {
    int t = blockIdx.x * 256 + threadIdx.x;
    if (t >= 27 * 128 * Cin) return;
    int ci = t % Cin;
    int co = (t / Cin) & 127;
    int tap = t / (Cin * 128);
    float v = w[(co * Cin + ci) * 27 + tap];
    __nv_bfloat16 h = __float2bfloat16(v);
    __nv_bfloat16 l = __float2bfloat16(v - __bfloat162float(h));
    int idx = ((tap * (Cin >> 5) + (ci >> 5)) * 128 + co) * 32 + (ci & 31);
    hi[idx] = h; lo[idx] = l;
}

// ============================ mma.sync conv3d ================================
// CTA: 256 thr = 8 warps. Output tile: [128 co] x [2x2 xy lines x 32 z].
// Warp (w): co half = (w>>2)*64, line = w&3. Acc d[4 m][4 n][4] fp32.
// SMEM: Xh/Xl [16 lines][34 z][36 ci-pad] bf16 ; Wh/Wl [128 co][36 pad] bf16.
#define XH_OFF 0
#define XL_OFF 39168
#define WH_OFF 78336
#define WL_OFF 87552
#define CONV_SMEM 96768
#define LSTRIDE 1224   // 34*36

__global__ __launch_bounds__(256, 2)
void conv3d_mma_kernel(const float* __restrict__ in,
                       const __nv_bfloat16* __restrict__ wbh,
                       const __nv_bfloat16* __restrict__ wbl,
                       const float* __restrict__ bias,
                       float* __restrict__ out, int Cin) {
    extern __shared__ char smem[];
    __nv_bfloat16* Xh = (__nv_bfloat16*)(smem + XH_OFF);
    __nv_bfloat16* Xl = (__nv_bfloat16*)(smem + XL_OFF);
    __nv_bfloat16* Wh = (__nv_bfloat16*)(smem + WH_OFF);
    __nv_bfloat16* Wl = (__nv_bfloat16*)(smem + WL_OFF);

    int tid = threadIdx.x, wid = tid >> 5, lane = tid & 31;
    int bx = blockIdx.x, b = blockIdx.y;
    int x0 = (bx >> 4) * 2, y0 = (bx & 15) * 2;
    int nch = Cin >> 5;

    int line = wid & 3;
    int cobase = (wid >> 2) * 64;
    int g = lane >> 2, t4 = lane & 3;

    float d[4][4][4];
    #pragma unroll
    for (int m = 0; m < 4; m++)
        #pragma unroll
        for (int n = 0; n < 4; n++)
            #pragma unroll
            for (int r = 0; r < 4; r++) d[m][n][r] = 0.f;

    const __nv_bfloat16 bz = __float2bfloat16(0.f);

    for (int ch = 0; ch < nch; ch++) {
        __syncthreads();   // all warps done with previous chunk's X
        // zero z-halo rows (z_smem = 0 and 33)
        for (int i = tid; i < 1024; i += 256) {
            int ci = i & 31, r2 = (i >> 5) & 1, il = i >> 6;
            int off = il * LSTRIDE + (r2 ? 33 : 0) * 36 + ci;
            Xh[off] = bz; Xl[off] = bz;
        }
        // stage X: 16 lines x 32 ci x 8 z-quads
        int c0 = ch * 32;
        for (int i = tid; i < 4096; i += 256) {
            int zq = i & 7, ci = (i >> 3) & 31, il = i >> 8;
            int gx = x0 - 1 + (il >> 2), gy = y0 - 1 + (il & 3);
            float4 v = make_float4(0.f, 0.f, 0.f, 0.f);
            if ((unsigned)gx < 32u && (unsigned)gy < 32u)
                v = *(const float4*)&in[(((size_t)(b * Cin + c0 + ci) * 32 + gx) * 32 + gy) * 32 + zq * 4];
            int base = il * LSTRIDE + (zq * 4 + 1) * 36 + ci;
            #pragma unroll
            for (int j = 0; j < 4; j++) {
                float f = (&v.x)[j];
                __nv_bfloat16 h = __float2bfloat16(f);
                Xh[base + j * 36] = h;
                Xl[base + j * 36] = __float2bfloat16(f - __bfloat162float(h));
            }
        }

        for (int tap = 0; tap < 27; tap++) {
            __syncthreads();   // protect W (and first-tap X visibility)
            {   // stage W[tap][ch]: 128x32 hi/lo with pad-36 rows
                const uint2* sh = (const uint2*)(wbh + (size_t)(tap * nch + ch) * 4096);
                const uint2* sl = (const uint2*)(wbl + (size_t)(tap * nch + ch) * 4096);
                for (int i = tid; i < 1024; i += 256) {
                    int co = i >> 3, c4 = (i & 7) * 4;
                    *(uint2*)&Wh[co * 36 + c4] = sh[i];
                    *(uint2*)&Wl[co * 36 + c4] = sl[i];
                }
            }
            __syncthreads();

            int dz = tap % 3, dy = (tap / 3) % 3, dx = tap / 9;
            int il = ((line >> 1) + dx) * 4 + (line & 1) + dy;
            const __nv_bfloat16* Xhb = Xh + il * LSTRIDE;
            const __nv_bfloat16* Xlb = Xl + il * LSTRIDE;

            #pragma unroll
            for (int k = 0; k < 2; k++) {
                uint32_t bh[4][2], bl[4][2];
                #pragma unroll
                for (int n = 0; n < 4; n++) {
                    int off = (n * 8 + g + dz) * 36 + t4 * 2 + k * 16;
                    bh[n][0] = *(const uint32_t*)(Xhb + off);
                    bh[n][1] = *(const uint32_t*)(Xhb + off + 8);
                    bl[n][0] = *(const uint32_t*)(Xlb + off);
                    bl[n][1] = *(const uint32_t*)(Xlb + off + 8);
                }
                #pragma unroll
                for (int m = 0; m < 4; m++) {
                    int woff = (cobase + m * 16 + g) * 36 + t4 * 2 + k * 16;
                    uint32_t ah0 = *(const uint32_t*)(Wh + woff);
                    uint32_t ah1 = *(const uint32_t*)(Wh + woff + 8 * 36);
                    uint32_t ah2 = *(const uint32_t*)(Wh + woff + 8);
                    uint32_t ah3 = *(const uint32_t*)(Wh + woff + 8 * 36 + 8);
                    uint32_t al0 = *(const uint32_t*)(Wl + woff);
                    uint32_t al1 = *(const uint32_t*)(Wl + woff + 8 * 36);
                    uint32_t al2 = *(const uint32_t*)(Wl + woff + 8);
                    uint32_t al3 = *(const uint32_t*)(Wl + woff + 8 * 36 + 8);
                    #pragma unroll
                    for (int n = 0; n < 4; n++) {
                        MMA_B16(d[m][n], ah0, ah1, ah2, ah3, bh[n][0], bh[n][1]);
                        MMA_B16(d[m][n], al0, al1, al2, al3, bh[n][0], bh[n][1]);
                        MMA_B16(d[m][n], ah0, ah1, ah2, ah3, bl[n][0], bl[n][1]);
                    }
                }
            }
        }
    }

    // epilogue: d frag rows = co (g, g+8), cols = z (2*t4, +1)
    int ox = x0 + (line >> 1), oy = y0 + (line & 1);
    #pragma unroll
    for (int m = 0; m < 4; m++) {
        int co = cobase + m * 16 + g;
        float bv0 = bias[co], bv1 = bias[co + 8];
        float* p0 = out + ((size_t)(b * COUT_ + co)) * R3_ + ox * 1024 + oy * 32;
        float* p1 = p0 + (size_t)8 * R3_;
        #pragma unroll
        for (int n = 0; n < 4; n++) {
            int z = n * 8 + t4 * 2;
            *(float2*)(p0 + z) = make_float2(d[m][n][0] + bv0, d[m][n][1] + bv0);
            *(float2*)(p1 + z) = make_float2(d[m][n][2] + bv1, d[m][n][3] + bv1);
        }
    }
}

// ---------------- GroupNorm stats ----------------
__global__ void gn_stats_kernel(const float* __restrict__ x, int S,
                                float* __restrict__ mean, float* __restrict__ rstd) {
    int bg = blockIdx.x;
    const float* p = x + (long)bg * 16 * S;
    int n = 16 * S;
    float s = 0.f, s2 = 0.f;
    for (int i = threadIdx.x; i < n; i += blockDim.x) {
        float v = p[i];
        s += v; s2 += v * v;
    }
    __shared__ float ra[512], rb[512];
    int tid = threadIdx.x;
    ra[tid] = s; rb[tid] = s2; __syncthreads();
    for (int st = 256; st > 0; st >>= 1) {
        if (tid < st) { ra[tid] += ra[tid + st]; rb[tid] += rb[tid + st]; }
        __syncthreads();
    }
    if (tid == 0) {
        float m = ra[0] / (float)n;
        float var = rb[0] / (float)n - m * m;
        mean[bg] = m;
        rstd[bg] = rsqrtf(var + GN_EPS_);
    }
}

__global__ void gn_apply_kernel(float* __restrict__ x, const float* __restrict__ gamma,
                                const float* __restrict__ beta,
                                const float* __restrict__ mean, const float* __restrict__ rstd,
                                int S) {
    int t = blockIdx.x * blockDim.x + threadIdx.x;
    int c = (t / S) % COUT_;
    int b = t / (S * COUT_);
    int idx = b * NG_ + (c >> 4);
    float y = (x[t] - mean[idx]) * rstd[idx] * gamma[c] + beta[c];
    x[t] = y / (1.0f + expf(-y));
}

__global__ void ptgemm_kernel(const float* __restrict__ f, const float* __restrict__ w,
                              const float* __restrict__ bias, float* __restrict__ pf) {
    int t = blockIdx.x * blockDim.x + threadIdx.x;
    int n = t & (N_ - 1);
    int r = t >> 12;
    int o = (r & 31) * 4;
    int b = r >> 5;
    float a0 = bias[o], a1 = bias[o + 1], a2 = bias[o + 2], a3 = bias[o + 3];
    const float* fb = f + (b * CIN_) * N_ + n;
    const float* w0 = w + o * CIN_;
    #pragma unroll 8
    for (int c = 0; c < CIN_; c++) {
        float fv = fb[c * N_];
        a0 += w0[c] * fv;
        a1 += w0[CIN_ + c] * fv;
        a2 += w0[2 * CIN_ + c] * fv;
        a3 += w0[3 * CIN_ + c] * fv;
    }
    float* op = &pf[(b * COUT_ + o) * N_ + n];
    op[0] = a0; op[N_] = a1; op[2 * N_] = a2; op[3 * N_] = a3;
}

__global__ void final_kernel(const float* __restrict__ nc, const float* __restrict__ h2,
                             const float* __restrict__ pf, const float* __restrict__ gamma,
                             const float* __restrict__ beta,
                             const float* __restrict__ mean, const float* __restrict__ rstd,
                             float* __restrict__ out) {
    int t = blockIdx.x * blockDim.x + threadIdx.x;
    int n = t & (N_ - 1);
    int r = t >> 12;
    int o = (r & 31) * 4;
    int b = r >> 5;

    float ncx = nc[(b * N_ + n) * 3 + 0];
    float ncy = nc[(b * N_ + n) * 3 + 1];
    float ncz = nc[(b * N_ + n) * 3 + 2];
    float fx = floorf(ncx), fy = floorf(ncy), fz = floorf(ncz);
    float dx = ncx - fx, dy = ncy - fy, dz = ncz - fz;
    int ix0 = (int)fx, iy0 = (int)fy, iz0 = (int)fz;
    int ix1 = min(ix0 + 1, R_ - 1), iy1 = min(iy0 + 1, R_ - 1), iz1 = min(iz0 + 1, R_ - 1);
    float wx[2] = {1.f - dx, dx}, wy[2] = {1.f - dy, dy}, wz[2] = {1.f - dz, dz};
    int xs[2] = {ix0, ix1}, ys[2] = {iy0, iy1}, zs[2] = {iz0, iz1};

    float d0 = 0.f, d1 = 0.f, d2 = 0.f, d3 = 0.f;
    const float* hb = &h2[(b * COUT_ + o) * R3_];
    #pragma unroll
    for (int k = 0; k < 8; k++) {
        int kx = k >> 2, ky = (k >> 1) & 1, kz = k & 1;
        float wk = wx[kx] * wy[ky] * wz[kz];
        int id = (xs[kx] * R_ + ys[ky]) * R_ + zs[kz];
        d0 += wk * hb[id];
        d1 += wk * hb[R3_ + id];
        d2 += wk * hb[2 * R3_ + id];
        d3 += wk * hb[3 * R3_ + id];
    }

    int idx = b * NG_ + (o >> 4);
    float m = mean[idx], rs = rstd[idx];
    const float* pp = &pf[(b * COUT_ + o) * N_ + n];
    float* op = &out[(b * COUT_ + o) * N_ + n];
    float dv[4] = {d0, d1, d2, d3};
    #pragma unroll
    for (int j = 0; j < 4; j++) {
        int c = o + j;
        float y = (pp[j * N_] - m) * rs * gamma[c] + beta[c];
        op[j * N_] = dv[j] + y / (1.0f + expf(-y));
    }
}

// ---------------- host launcher ----------------------------------------------
extern "C" void kernel_launch(void* const* d_in, const int* in_sizes, int n_in,
                              void* d_out, int out_size) {
    const float* features = (const float*)d_in[0];
    const float* coords   = (const float*)d_in[1];
    const float* c1w = (const float*)d_in[2];
    const float* c1b = (const float*)d_in[3];
    const float* g1g = (const float*)d_in[4];
    const float* g1b = (const float*)d_in[5];
    const float* c2w = (const float*)d_in[6];
    const float* c2b = (const float*)d_in[7];
    const float* g2g = (const float*)d_in[8];
    const float* g2b = (const float*)d_in[9];
    const float* ptw = (const float*)d_in[10];
    const float* ptb = (const float*)d_in[11];
    const float* pgg = (const float*)d_in[12];
    const float* pgb = (const float*)d_in[13];
    float* out = (float*)d_out;

    float *grid_p, *cnt_p, *h1, *h2, *pf, *nc, *mean_p, *rstd_p;
    int* vox_p;
    __nv_bfloat16 *w1h, *w1l, *w2h, *w2l;
    cudaGetSymbolAddress((void**)&grid_p, g_grid);
    cudaGetSymbolAddress((void**)&cnt_p, g_cnt);
    cudaGetSymbolAddress((void**)&vox_p, g_vox);
    cudaGetSymbolAddress((void**)&nc, g_nc);
    cudaGetSymbolAddress((void**)&h1, g_h1);
    cudaGetSymbolAddress((void**)&h2, g_h2);
    cudaGetSymbolAddress((void**)&pf, g_pf);
    cudaGetSymbolAddress((void**)&mean_p, g_mean);
    cudaGetSymbolAddress((void**)&rstd_p, g_rstd);
    cudaGetSymbolAddress((void**)&w1h, g_w1h);
    cudaGetSymbolAddress((void**)&w1l, g_w1l);
    cudaGetSymbolAddress((void**)&w2h, g_w2h);
    cudaGetSymbolAddress((void**)&w2l, g_w2l);

    cudaFuncSetAttribute(conv3d_mma_kernel,
                         cudaFuncAttributeMaxDynamicSharedMemorySize, CONV_SMEM);

    zero_kernel<<<4096, 256>>>(grid_p, cnt_p);
    coords_kernel<<<B_, 256>>>(coords, nc, vox_p, cnt_p);
    scatter_kernel<<<8192, 256>>>(features, vox_p, grid_p);
    normgrid_kernel<<<65536, 256>>>(grid_p, cnt_p);
    wprep_kernel<<<(27 * 128 * CIN_ + 255) / 256, 256>>>(c1w, w1h, w1l, CIN_);
    wprep_kernel<<<(27 * 128 * COUT_ + 255) / 256, 256>>>(c2w, w2h, w2l, COUT_);

    conv3d_mma_kernel<<<dim3(256, 8), 256, CONV_SMEM>>>(grid_p, w1h, w1l, c1b, h1, CIN_);
    gn_stats_kernel<<<B_ * NG_, 512>>>(h1, R3_, mean_p, rstd_p);
    gn_apply_kernel<<<131072, 256>>>(h1, g1g, g1b, mean_p, rstd_p, R3_);

    conv3d_mma_kernel<<<dim3(256, 8), 256, CONV_SMEM>>>(h1, w2h, w2l, c2b, h2, COUT_);
    gn_stats_kernel<<<B_ * NG_, 512>>>(h2, R3_, mean_p, rstd_p);
    gn_apply_kernel<<<131072, 256>>>(h2, g2g, g2b, mean_p, rstd_p, R3_);

    ptgemm_kernel<<<4096, 256>>>(features, ptw, ptb, pf);
    gn_stats_kernel<<<B_ * NG_, 512>>>(pf, N_, mean_p, rstd_p);
    final_kernel<<<4096, 256>>>(nc, h2, pf, pgg, pgb, mean_p, rstd_p, out);
}

// round 6
// speedup vs baseline: 4.1696x; 1.2024x over previous
#include <cuda_runtime.h>
#include <cuda_bf16.h>
#include <math.h>
#include <stdint.h>

#define B_    8
#define N_    4096
#define CIN_  64
#define COUT_ 128
#define R_    32
#define R3_   32768
#define NG_   8
#define GN_EPS_ 1e-5f

// ---------------- scratch (static device globals; no allocation) -------------
static __device__ float g_grid[B_ * CIN_ * R3_];
static __device__ float g_cnt [B_ * R3_];
static __device__ int   g_vox [B_ * N_];
static __device__ float g_nc  [B_ * N_ * 3];
static __device__ float g_h1  [B_ * COUT_ * R3_];
static __device__ float g_h2  [B_ * COUT_ * R3_];
static __device__ float g_pf  [B_ * COUT_ * N_];
static __device__ float g_mean[B_ * NG_];
static __device__ float g_rstd[B_ * NG_];
// pre-split weights: [tap][ci-chunk32][co 128][ci 32] bf16, hi/lo planes
static __device__ __nv_bfloat16 g_w1h[27 * 2 * 128 * 32];
static __device__ __nv_bfloat16 g_w1l[27 * 2 * 128 * 32];
static __device__ __nv_bfloat16 g_w2h[27 * 4 * 128 * 32];
static __device__ __nv_bfloat16 g_w2l[27 * 4 * 128 * 32];

// ---------------- mma.sync m16n8k16 bf16 ------------------------------------
#define MMA_B16(dd, a0, a1, a2, a3, b0, b1) \
    asm volatile("mma.sync.aligned.m16n8k16.row.col.f32.bf16.bf16.f32 " \
        "{%0,%1,%2,%3}, {%4,%5,%6,%7}, {%8,%9}, {%0,%1,%2,%3};" \
        : "+f"((dd)[0]), "+f"((dd)[1]), "+f"((dd)[2]), "+f"((dd)[3]) \
        : "r"(a0), "r"(a1), "r"(a2), "r"(a3), "r"(b0), "r"(b1))

__device__ __forceinline__ void ldsm4(uint32_t* r, uint32_t addr) {
    asm volatile("ldmatrix.sync.aligned.m8n8.x4.shared.b16 {%0,%1,%2,%3}, [%4];"
        : "=r"(r[0]), "=r"(r[1]), "=r"(r[2]), "=r"(r[3]) : "r"(addr));
}
__device__ __forceinline__ uint32_t smem_u32(const void* p) {
    uint32_t a;
    asm("{ .reg .u64 t; cvta.to.shared.u64 t, %1; cvt.u32.u64 %0, t; }" : "=r"(a) : "l"(p));
    return a;
}

// ============================ elementwise kernels ============================
__global__ void zero_kernel(float* __restrict__ grid, float* __restrict__ cnt) {
    int stride = gridDim.x * blockDim.x;
    int t0 = blockIdx.x * blockDim.x + threadIdx.x;
    for (int i = t0; i < B_ * CIN_ * R3_; i += stride) grid[i] = 0.f;
    for (int i = t0; i < B_ * R3_; i += stride) cnt[i] = 0.f;
}

__global__ void coords_kernel(const float* __restrict__ coords,
                              float* __restrict__ nc, int* __restrict__ vox,
                              float* __restrict__ cnt) {
    int b = blockIdx.x, tid = threadIdx.x;
    __shared__ float red[256];
    __shared__ float smean[3];
    __shared__ float sinv;

    float s0 = 0.f, s1 = 0.f, s2 = 0.f;
    for (int n = tid; n < N_; n += 256) {
        const float* c = &coords[(b * N_ + n) * 3];
        s0 += c[0]; s1 += c[1]; s2 += c[2];
    }
    float ss[3] = {s0, s1, s2};
    for (int d = 0; d < 3; d++) {
        red[tid] = ss[d]; __syncthreads();
        for (int st = 128; st > 0; st >>= 1) {
            if (tid < st) red[tid] += red[tid + st];
            __syncthreads();
        }
        if (tid == 0) smean[d] = red[0] * (1.0f / N_);
        __syncthreads();
    }
    float m0 = smean[0], m1 = smean[1], m2 = smean[2];

    float mx = 0.f;
    for (int n = tid; n < N_; n += 256) {
        const float* c = &coords[(b * N_ + n) * 3];
        float dx = c[0] - m0, dy = c[1] - m1, dz = c[2] - m2;
        mx = fmaxf(mx, dx * dx + dy * dy + dz * dz);
    }
    red[tid] = mx; __syncthreads();
    for (int st = 128; st > 0; st >>= 1) {
        if (tid < st) red[tid] = fmaxf(red[tid], red[tid + st]);
        __syncthreads();
    }
    if (tid == 0) sinv = 1.0f / (2.0f * sqrtf(red[0]));
    __syncthreads();
    float inv = sinv;

    for (int n = tid; n < N_; n += 256) {
        const float* c = &coords[(b * N_ + n) * 3];
        float v[3]; int iv[3];
        float cc[3] = {c[0] - m0, c[1] - m1, c[2] - m2};
        #pragma unroll
        for (int d = 0; d < 3; d++) {
            float x = (cc[d] * inv + 0.5f) * (float)R_;
            x = fminf(fmaxf(x, 0.f), (float)(R_ - 1));
            v[d] = x;
            iv[d] = (int)rintf(x);
        }
        nc[(b * N_ + n) * 3 + 0] = v[0];
        nc[(b * N_ + n) * 3 + 1] = v[1];
        nc[(b * N_ + n) * 3 + 2] = v[2];
        int flat = (iv[0] * R_ + iv[1]) * R_ + iv[2];
        vox[b * N_ + n] = flat;
        atomicAdd(&cnt[b * R3_ + flat], 1.0f);
    }
}

__global__ void scatter_kernel(const float* __restrict__ f,
                               const int* __restrict__ vox,
                               float* __restrict__ grid) {
    int t = blockIdx.x * blockDim.x + threadIdx.x;
    int n = t & (N_ - 1);
    int bc = t >> 12;
    int b = bc >> 6;
    int flat = vox[b * N_ + n];
    atomicAdd(&grid[bc * R3_ + flat], f[t]);
}

__global__ void normgrid_kernel(float* __restrict__ grid, const float* __restrict__ cnt) {
    int t = blockIdx.x * blockDim.x + threadIdx.x;
    int v = t & (R3_ - 1);
    int b = t >> 21;
    float c = cnt[b * R3_ + v];
    grid[t] = grid[t] / fmaxf(c, 1.0f);
}

// ---------------- weight prep: fp32 -> bf16 hi/lo ---------------------------
__global__ void wprep_kernel(const float* __restrict__ w, __nv_bfloat16* __restrict__ hi,
                             __nv_bfloat16* __restrict__ lo, int Cin) {
    int t = blockIdx.x * 256 + threadIdx.x;
    if (t >= 27 * 128 * Cin) return;
    int ci = t % Cin;
    int co = (t / Cin) & 127;
    int tap = t / (Cin * 128);
    float v = w[(co * Cin + ci) * 27 + tap];
    __nv_bfloat16 h = __float2bfloat16(v);
    __nv_bfloat16 l = __float2bfloat16(v - __bfloat162float(h));
    int idx = ((tap * (Cin >> 5) + (ci >> 5)) * 128 + co) * 32 + (ci & 31);
    hi[idx] = h; lo[idx] = l;
}

// ============================ mma.sync conv3d ================================
// CTA: 512 thr = 16 warps. Output tile: [128 co] x [4x2 xy lines x 32 z].
// Warp w: line = w&7 (lx=line>>1, ly=line&1), co half = (w>>3)*64.
// SMEM (bf16, row pad 40 elems = 80B, 16B-aligned rows for ldmatrix):
//   Xh [24 line tiles][34 z][40]  at 0       (65,280 B)
//   Xl same                        at 65,280
//   W double buffer: per buf hi[128][40] + lo[128][40] = 20,480 B, at 130,560
#define LSTRB   2720            // line tile stride bytes (34*40*2)
#define XL_OFF  65280
#define W_OFF   130560
#define WBUF    20480
#define WLO     10240
#define CONV_SMEM 171520

__global__ __launch_bounds__(512, 1)
void conv3d_mma_kernel(const float* __restrict__ in,
                       const __nv_bfloat16* __restrict__ wbh,
                       const __nv_bfloat16* __restrict__ wbl,
                       const float* __restrict__ bias,
                       float* __restrict__ out, int Cin) {
    extern __shared__ __align__(16) char smem[];
    __nv_bfloat16* Xh = (__nv_bfloat16*)smem;
    __nv_bfloat16* Xl = (__nv_bfloat16*)(smem + XL_OFF);
    uint32_t sb = smem_u32(smem);
    uint32_t xh_u = sb, xl_u = sb + XL_OFF, w_u = sb + W_OFF;

    int tid = threadIdx.x, wid = tid >> 5, lane = tid & 31;
    int bx = blockIdx.x, b = blockIdx.y;
    int x0 = (bx >> 4) * 4, y0 = (bx & 15) * 2;
    int nch = Cin >> 5;
    int line = wid & 7;
    int cobase = (wid >> 3) * 64;
    int g = lane >> 2, t4 = lane & 3;

    // per-lane ldmatrix byte offsets
    uint32_t a_off = ((uint32_t)((lane & 7) + ((lane >> 3) & 1) * 8) * 40
                      + (uint32_t)(lane >> 4) * 8) * 2;
    uint32_t b_off = ((uint32_t)((lane & 7) + (lane >> 4) * 8) * 40
                      + (uint32_t)((lane >> 3) & 1) * 8) * 2;

    // W staging coords (per thread): 128 co x 4 quads
    int wco = tid >> 2, wq = tid & 3;
    uint32_t wdst = (uint32_t)wco * 80 + (uint32_t)wq * 16;
    int wsrc = wco * 4 + wq;   // uint4 index within a 128x32 plane

    float d[4][4][4];
    #pragma unroll
    for (int m = 0; m < 4; m++)
        #pragma unroll
        for (int n = 0; n < 4; n++)
            #pragma unroll
            for (int r = 0; r < 4; r++) d[m][n][r] = 0.f;

    const __nv_bfloat16 bz = __float2bfloat16(0.f);

    for (int ch = 0; ch < nch; ch++) {
        __syncthreads();   // all warps done reading previous chunk's X + W
        // zero z-halo rows (z_smem = 0 and 33), cols 0..31
        for (int i = tid; i < 1536; i += 512) {
            int ci = i & 31, r2 = (i >> 5) & 1, il = i >> 6;
            int off = il * 1360 + (r2 ? 33 : 0) * 40 + ci;
            Xh[off] = bz; Xl[off] = bz;
        }
        // stage X: 24 line tiles x 32 ci x 8 z-quads
        int c0 = ch * 32;
        for (int i = tid; i < 6144; i += 512) {
            int zq = i & 7, ci = (i >> 3) & 31, il = i >> 8;
            int gx = x0 - 1 + (il >> 2), gy = y0 - 1 + (il & 3);
            float4 v = make_float4(0.f, 0.f, 0.f, 0.f);
            if ((unsigned)gx < 32u && (unsigned)gy < 32u)
                v = *(const float4*)&in[(((size_t)(b * Cin + c0 + ci) * 32 + gx) * 32 + gy) * 32 + zq * 4];
            int base = il * 1360 + (zq * 4 + 1) * 40 + ci;
            #pragma unroll
            for (int j = 0; j < 4; j++) {
                float f = (&v.x)[j];
                __nv_bfloat16 h = __float2bfloat16(f);
                Xh[base + j * 40] = h;
                Xl[base + j * 40] = __float2bfloat16(f - __bfloat162float(h));
            }
        }
        // stage W[tap=0] into buf 0
        {
            const uint4* sh = (const uint4*)(wbh + (size_t)(0 * nch + ch) * 4096);
            const uint4* sl = (const uint4*)(wbl + (size_t)(0 * nch + ch) * 4096);
            *(uint4*)(smem + W_OFF + wdst) = sh[wsrc];
            *(uint4*)(smem + W_OFF + WLO + wdst) = sl[wsrc];
        }
        __syncthreads();

        for (int tap = 0; tap < 27; tap++) {
            int buf = tap & 1;
            uint4 nh, nl;
            bool pre = (tap < 26);
            if (pre) {   // prefetch next tap's W into registers (overlaps MMAs)
                const uint4* sh = (const uint4*)(wbh + (size_t)((tap + 1) * nch + ch) * 4096);
                const uint4* sl = (const uint4*)(wbl + (size_t)((tap + 1) * nch + ch) * 4096);
                nh = sh[wsrc]; nl = sl[wsrc];
            }

            int dz = tap % 3, dyy = (tap / 3) % 3, dxx = tap / 9;
            int il = ((line >> 1) + dxx) * 4 + (line & 1) + dyy;
            uint32_t xb = (uint32_t)il * LSTRB + (uint32_t)dz * 80;
            uint32_t wb = w_u + (uint32_t)buf * WBUF + (uint32_t)cobase * 80;

            #pragma unroll
            for (int k = 0; k < 2; k++) {
                uint32_t BH[8], BL[8];
                #pragma unroll
                for (int np = 0; np < 2; np++) {
                    uint32_t ba = xb + (uint32_t)np * 1280 + (uint32_t)k * 32 + b_off;
                    ldsm4(&BH[np * 4], xh_u + ba);
                    ldsm4(&BL[np * 4], xl_u + ba);
                }
                #pragma unroll
                for (int m = 0; m < 4; m++) {
                    uint32_t AH[4], AL[4];
                    uint32_t aa = wb + (uint32_t)m * 1280 + (uint32_t)k * 32 + a_off;
                    ldsm4(AH, aa);
                    ldsm4(AL, aa + WLO);
                    #pragma unroll
                    for (int n = 0; n < 4; n++) {
                        MMA_B16(d[m][n], AH[0], AH[1], AH[2], AH[3], BH[n * 2], BH[n * 2 + 1]);
                        MMA_B16(d[m][n], AL[0], AL[1], AL[2], AL[3], BH[n * 2], BH[n * 2 + 1]);
                        MMA_B16(d[m][n], AH[0], AH[1], AH[2], AH[3], BL[n * 2], BL[n * 2 + 1]);
                    }
                }
            }

            if (pre) {
                char* dst = smem + W_OFF + (buf ^ 1) * WBUF;
                *(uint4*)(dst + wdst) = nh;
                *(uint4*)(dst + WLO + wdst) = nl;
            }
            __syncthreads();
        }
    }

    // epilogue: frag rows = co (g, g+8), cols = z (n*8 + 2*t4, +1)
    int ox = x0 + (line >> 1), oy = y0 + (line & 1);
    #pragma unroll
    for (int m = 0; m < 4; m++) {
        int co = cobase + m * 16 + g;
        float bv0 = bias[co], bv1 = bias[co + 8];
        float* p0 = out + ((size_t)(b * COUT_ + co)) * R3_ + ox * 1024 + oy * 32;
        float* p1 = p0 + (size_t)8 * R3_;
        #pragma unroll
        for (int n = 0; n < 4; n++) {
            int z = n * 8 + t4 * 2;
            *(float2*)(p0 + z) = make_float2(d[m][n][0] + bv0, d[m][n][1] + bv0);
            *(float2*)(p1 + z) = make_float2(d[m][n][2] + bv1, d[m][n][3] + bv1);
        }
    }
}

// ---------------- GroupNorm stats ----------------
__global__ void gn_stats_kernel(const float* __restrict__ x, int S,
                                float* __restrict__ mean, float* __restrict__ rstd) {
    int bg = blockIdx.x;
    const float* p = x + (long)bg * 16 * S;
    int n = 16 * S;
    float s = 0.f, s2 = 0.f;
    for (int i = threadIdx.x; i < n; i += blockDim.x) {
        float v = p[i];
        s += v; s2 += v * v;
    }
    __shared__ float ra[512], rb[512];
    int tid = threadIdx.x;
    ra[tid] = s; rb[tid] = s2; __syncthreads();
    for (int st = 256; st > 0; st >>= 1) {
        if (tid < st) { ra[tid] += ra[tid + st]; rb[tid] += rb[tid + st]; }
        __syncthreads();
    }
    if (tid == 0) {
        float m = ra[0] / (float)n;
        float var = rb[0] / (float)n - m * m;
        mean[bg] = m;
        rstd[bg] = rsqrtf(var + GN_EPS_);
    }
}

__global__ void gn_apply_kernel(float* __restrict__ x, const float* __restrict__ gamma,
                                const float* __restrict__ beta,
                                const float* __restrict__ mean, const float* __restrict__ rstd,
                                int S) {
    int t = blockIdx.x * blockDim.x + threadIdx.x;
    int c = (t / S) % COUT_;
    int b = t / (S * COUT_);
    int idx = b * NG_ + (c >> 4);
    float y = (x[t] - mean[idx]) * rstd[idx] * gamma[c] + beta[c];
    x[t] = y / (1.0f + expf(-y));
}

__global__ void ptgemm_kernel(const float* __restrict__ f, const float* __restrict__ w,
                              const float* __restrict__ bias, float* __restrict__ pf) {
    int t = blockIdx.x * blockDim.x + threadIdx.x;
    int n = t & (N_ - 1);
    int r = t >> 12;
    int o = (r & 31) * 4;
    int b = r >> 5;
    float a0 = bias[o], a1 = bias[o + 1], a2 = bias[o + 2], a3 = bias[o + 3];
    const float* fb = f + (b * CIN_) * N_ + n;
    const float* w0 = w + o * CIN_;
    #pragma unroll 8
    for (int c = 0; c < CIN_; c++) {
        float fv = fb[c * N_];
        a0 += w0[c] * fv;
        a1 += w0[CIN_ + c] * fv;
        a2 += w0[2 * CIN_ + c] * fv;
        a3 += w0[3 * CIN_ + c] * fv;
    }
    float* op = &pf[(b * COUT_ + o) * N_ + n];
    op[0] = a0; op[N_] = a1; op[2 * N_] = a2; op[3 * N_] = a3;
}

__global__ void final_kernel(const float* __restrict__ nc, const float* __restrict__ h2,
                             const float* __restrict__ pf, const float* __restrict__ gamma,
                             const float* __restrict__ beta,
                             const float* __restrict__ mean, const float* __restrict__ rstd,
                             float* __restrict__ out) {
    int t = blockIdx.x * blockDim.x + threadIdx.x;
    int n = t & (N_ - 1);
    int r = t >> 12;
    int o = (r & 31) * 4;
    int b = r >> 5;

    float ncx = nc[(b * N_ + n) * 3 + 0];
    float ncy = nc[(b * N_ + n) * 3 + 1];
    float ncz = nc[(b * N_ + n) * 3 + 2];
    float fx = floorf(ncx), fy = floorf(ncy), fz = floorf(ncz);
    float dx = ncx - fx, dy = ncy - fy, dz = ncz - fz;
    int ix0 = (int)fx, iy0 = (int)fy, iz0 = (int)fz;
    int ix1 = min(ix0 + 1, R_ - 1), iy1 = min(iy0 + 1, R_ - 1), iz1 = min(iz0 + 1, R_ - 1);
    float wx[2] = {1.f - dx, dx}, wy[2] = {1.f - dy, dy}, wz[2] = {1.f - dz, dz};
    int xs[2] = {ix0, ix1}, ys[2] = {iy0, iy1}, zs[2] = {iz0, iz1};

    float d0 = 0.f, d1 = 0.f, d2 = 0.f, d3 = 0.f;
    const float* hb = &h2[(b * COUT_ + o) * R3_];
    #pragma unroll
    for (int k = 0; k < 8; k++) {
        int kx = k >> 2, ky = (k >> 1) & 1, kz = k & 1;
        float wk = wx[kx] * wy[ky] * wz[kz];
        int id = (xs[kx] * R_ + ys[ky]) * R_ + zs[kz];
        d0 += wk * hb[id];
        d1 += wk * hb[R3_ + id];
        d2 += wk * hb[2 * R3_ + id];
        d3 += wk * hb[3 * R3_ + id];
    }

    int idx = b * NG_ + (o >> 4);
    float m = mean[idx], rs = rstd[idx];
    const float* pp = &pf[(b * COUT_ + o) * N_ + n];
    float* op = &out[(b * COUT_ + o) * N_ + n];
    float dv[4] = {d0, d1, d2, d3};
    #pragma unroll
    for (int j = 0; j < 4; j++) {
        int c = o + j;
        float y = (pp[j * N_] - m) * rs * gamma[c] + beta[c];
        op[j * N_] = dv[j] + y / (1.0f + expf(-y));
    }
}

// ---------------- host launcher ----------------------------------------------
extern "C" void kernel_launch(void* const* d_in, const int* in_sizes, int n_in,
                              void* d_out, int out_size) {
    const float* features = (const float*)d_in[0];
    const float* coords   = (const float*)d_in[1];
    const float* c1w = (const float*)d_in[2];
    const float* c1b = (const float*)d_in[3];
    const float* g1g = (const float*)d_in[4];
    const float* g1b = (const float*)d_in[5];
    const float* c2w = (const float*)d_in[6];
    const float* c2b = (const float*)d_in[7];
    const float* g2g = (const float*)d_in[8];
    const float* g2b = (const float*)d_in[9];
    const float* ptw = (const float*)d_in[10];
    const float* ptb = (const float*)d_in[11];
    const float* pgg = (const float*)d_in[12];
    const float* pgb = (const float*)d_in[13];
    float* out = (float*)d_out;

    float *grid_p, *cnt_p, *h1, *h2, *pf, *nc, *mean_p, *rstd_p;
    int* vox_p;
    __nv_bfloat16 *w1h, *w1l, *w2h, *w2l;
    cudaGetSymbolAddress((void**)&grid_p, g_grid);
    cudaGetSymbolAddress((void**)&cnt_p, g_cnt);
    cudaGetSymbolAddress((void**)&vox_p, g_vox);
    cudaGetSymbolAddress((void**)&nc, g_nc);
    cudaGetSymbolAddress((void**)&h1, g_h1);
    cudaGetSymbolAddress((void**)&h2, g_h2);
    cudaGetSymbolAddress((void**)&pf, g_pf);
    cudaGetSymbolAddress((void**)&mean_p, g_mean);
    cudaGetSymbolAddress((void**)&rstd_p, g_rstd);
    cudaGetSymbolAddress((void**)&w1h, g_w1h);
    cudaGetSymbolAddress((void**)&w1l, g_w1l);
    cudaGetSymbolAddress((void**)&w2h, g_w2h);
    cudaGetSymbolAddress((void**)&w2l, g_w2l);

    cudaFuncSetAttribute(conv3d_mma_kernel,
                         cudaFuncAttributeMaxDynamicSharedMemorySize, CONV_SMEM);

    zero_kernel<<<4096, 256>>>(grid_p, cnt_p);
    coords_kernel<<<B_, 256>>>(coords, nc, vox_p, cnt_p);
    scatter_kernel<<<8192, 256>>>(features, vox_p, grid_p);
    normgrid_kernel<<<65536, 256>>>(grid_p, cnt_p);
    wprep_kernel<<<(27 * 128 * CIN_ + 255) / 256, 256>>>(c1w, w1h, w1l, CIN_);
    wprep_kernel<<<(27 * 128 * COUT_ + 255) / 256, 256>>>(c2w, w2h, w2l, COUT_);

    conv3d_mma_kernel<<<dim3(128, 8), 512, CONV_SMEM>>>(grid_p, w1h, w1l, c1b, h1, CIN_);
    gn_stats_kernel<<<B_ * NG_, 512>>>(h1, R3_, mean_p, rstd_p);
    gn_apply_kernel<<<131072, 256>>>(h1, g1g, g1b, mean_p, rstd_p, R3_);

    conv3d_mma_kernel<<<dim3(128, 8), 512, CONV_SMEM>>>(h1, w2h, w2l, c2b, h2, COUT_);
    gn_stats_kernel<<<B_ * NG_, 512>>>(h2, R3_, mean_p, rstd_p);
    gn_apply_kernel<<<131072, 256>>>(h2, g2g, g2b, mean_p, rstd_p, R3_);

    ptgemm_kernel<<<4096, 256>>>(features, ptw, ptb, pf);
    gn_stats_kernel<<<B_ * NG_, 512>>>(pf, N_, mean_p, rstd_p);
    final_kernel<<<4096, 256>>>(nc, h2, pf, pgg, pgb, mean_p, rstd_p, out);
}

// round 7
// speedup vs baseline: 11.0244x; 2.6440x over previous
#include <cuda_runtime.h>
#include <cuda_fp16.h>
#include <math.h>
#include <stdint.h>

#define B_    8
#define N_    4096
#define CIN_  64
#define COUT_ 128
#define R_    32
#define R3_   32768
#define NG_   8
#define GN_EPS_ 1e-5f

// ---------------- scratch (static device globals; no allocation) -------------
static __device__ float g_grid[B_ * CIN_ * R3_];
static __device__ float g_cnt [B_ * R3_];
static __device__ int   g_vox [B_ * N_];
static __device__ float g_nc  [B_ * N_ * 3];
static __device__ float g_h1  [B_ * COUT_ * R3_];
static __device__ float g_h2  [B_ * COUT_ * R3_];
static __device__ float g_pf  [B_ * COUT_ * N_];
static __device__ float g_mean[B_ * NG_];
static __device__ float g_rstd[B_ * NG_];
static __device__ float g_sum [B_ * NG_];
static __device__ float g_sum2[B_ * NG_];
// fp16 weights: [tap][ci-chunk32][co 128][ci 32]
static __device__ __half g_w1[27 * 2 * 128 * 32];
static __device__ __half g_w2[27 * 4 * 128 * 32];

// ---------------- mma.sync m16n8k16 fp16 ------------------------------------
#define MMA_F16(dd, a0, a1, a2, a3, b0, b1) \
    asm volatile("mma.sync.aligned.m16n8k16.row.col.f32.f16.f16.f32 " \
        "{%0,%1,%2,%3}, {%4,%5,%6,%7}, {%8,%9}, {%0,%1,%2,%3};" \
        : "+f"((dd)[0]), "+f"((dd)[1]), "+f"((dd)[2]), "+f"((dd)[3]) \
        : "r"(a0), "r"(a1), "r"(a2), "r"(a3), "r"(b0), "r"(b1))

__device__ __forceinline__ void ldsm4(uint32_t* r, uint32_t addr) {
    asm volatile("ldmatrix.sync.aligned.m8n8.x4.shared.b16 {%0,%1,%2,%3}, [%4];"
        : "=r"(r[0]), "=r"(r[1]), "=r"(r[2]), "=r"(r[3]) : "r"(addr));
}
__device__ __forceinline__ uint32_t smem_u32(const void* p) {
    uint32_t a;
    asm("{ .reg .u64 t; cvta.to.shared.u64 t, %1; cvt.u32.u64 %0, t; }" : "=r"(a) : "l"(p));
    return a;
}

// ============================ elementwise kernels ============================
__global__ void zero_kernel(float* __restrict__ grid, float* __restrict__ cnt,
                            float* __restrict__ gs, float* __restrict__ gs2) {
    int stride = gridDim.x * blockDim.x;
    int t0 = blockIdx.x * blockDim.x + threadIdx.x;
    for (int i = t0; i < B_ * CIN_ * R3_; i += stride) grid[i] = 0.f;
    for (int i = t0; i < B_ * R3_; i += stride) cnt[i] = 0.f;
    if (t0 < B_ * NG_) { gs[t0] = 0.f; gs2[t0] = 0.f; }
}

__global__ void coords_kernel(const float* __restrict__ coords,
                              float* __restrict__ nc, int* __restrict__ vox,
                              float* __restrict__ cnt) {
    int b = blockIdx.x, tid = threadIdx.x;
    __shared__ float red[256];
    __shared__ float smean[3];
    __shared__ float sinv;

    float s0 = 0.f, s1 = 0.f, s2 = 0.f;
    for (int n = tid; n < N_; n += 256) {
        const float* c = &coords[(b * N_ + n) * 3];
        s0 += c[0]; s1 += c[1]; s2 += c[2];
    }
    float ss[3] = {s0, s1, s2};
    for (int d = 0; d < 3; d++) {
        red[tid] = ss[d]; __syncthreads();
        for (int st = 128; st > 0; st >>= 1) {
            if (tid < st) red[tid] += red[tid + st];
            __syncthreads();
        }
        if (tid == 0) smean[d] = red[0] * (1.0f / N_);
        __syncthreads();
    }
    float m0 = smean[0], m1 = smean[1], m2 = smean[2];

    float mx = 0.f;
    for (int n = tid; n < N_; n += 256) {
        const float* c = &coords[(b * N_ + n) * 3];
        float dx = c[0] - m0, dy = c[1] - m1, dz = c[2] - m2;
        mx = fmaxf(mx, dx * dx + dy * dy + dz * dz);
    }
    red[tid] = mx; __syncthreads();
    for (int st = 128; st > 0; st >>= 1) {
        if (tid < st) red[tid] = fmaxf(red[tid], red[tid + st]);
        __syncthreads();
    }
    if (tid == 0) sinv = 1.0f / (2.0f * sqrtf(red[0]));
    __syncthreads();
    float inv = sinv;

    for (int n = tid; n < N_; n += 256) {
        const float* c = &coords[(b * N_ + n) * 3];
        float v[3]; int iv[3];
        float cc[3] = {c[0] - m0, c[1] - m1, c[2] - m2};
        #pragma unroll
        for (int d = 0; d < 3; d++) {
            float x = (cc[d] * inv + 0.5f) * (float)R_;
            x = fminf(fmaxf(x, 0.f), (float)(R_ - 1));
            v[d] = x;
            iv[d] = (int)rintf(x);
        }
        nc[(b * N_ + n) * 3 + 0] = v[0];
        nc[(b * N_ + n) * 3 + 1] = v[1];
        nc[(b * N_ + n) * 3 + 2] = v[2];
        int flat = (iv[0] * R_ + iv[1]) * R_ + iv[2];
        vox[b * N_ + n] = flat;
        atomicAdd(&cnt[b * R3_ + flat], 1.0f);
    }
}

__global__ void scatter_kernel(const float* __restrict__ f,
                               const int* __restrict__ vox,
                               float* __restrict__ grid) {
    int t = blockIdx.x * blockDim.x + threadIdx.x;
    int n = t & (N_ - 1);
    int bc = t >> 12;
    int b = bc >> 6;
    int flat = vox[b * N_ + n];
    atomicAdd(&grid[bc * R3_ + flat], f[t]);
}

__global__ void normgrid_kernel(float* __restrict__ grid, const float* __restrict__ cnt) {
    int t = blockIdx.x * blockDim.x + threadIdx.x;
    int v = t & (R3_ - 1);
    int b = t >> 21;
    float c = cnt[b * R3_ + v];
    grid[t] = grid[t] / fmaxf(c, 1.0f);
}

// ---------------- weight prep: fp32 -> fp16 ----------------------------------
__global__ void wprep_kernel(const float* __restrict__ w, __half* __restrict__ wh, int Cin) {
    int t = blockIdx.x * 256 + threadIdx.x;
    if (t >= 27 * 128 * Cin) return;
    int ci = t % Cin;
    int co = (t / Cin) & 127;
    int tap = t / (Cin * 128);
    float v = w[(co * Cin + ci) * 27 + tap];
    int idx = ((tap * (Cin >> 5) + (ci >> 5)) * 128 + co) * 32 + (ci & 31);
    wh[idx] = __float2half_rn(v);
}

// ============================ mma.sync conv3d (fp16) =========================
// CTA: 256 thr = 8 warps. Output tile: [128 co] x [2x2 xy lines x 32 z].
// Warp w: line = w&3, co half = (w>>2)*64.
// SMEM: X [16 line tiles][34 z][40 pad] fp16 at 0 (43,520 B)
//       W double buffer [128][40] fp16 per buf (10,240 B) at 43,520
//       flags[16] int at 64,000
#define LSTRB   2720            // line tile stride bytes (34*40*2)
#define W_OFF   43520
#define WBUF    10240
#define FLG_OFF 64000
#define CONV_SMEM 64064

__global__ __launch_bounds__(256, 2)
void conv3d_mma_kernel(const float* __restrict__ in,
                       const __half* __restrict__ wgt,
                       const float* __restrict__ bias,
                       float* __restrict__ out, int Cin,
                       float* __restrict__ gs, float* __restrict__ gs2) {
    extern __shared__ __align__(16) char smem[];
    __half* X = (__half*)smem;
    int* flags = (int*)(smem + FLG_OFF);
    uint32_t sb = smem_u32(smem);
    uint32_t x_u = sb, w_u = sb + W_OFF;

    int tid = threadIdx.x, wid = tid >> 5, lane = tid & 31;
    int bx = blockIdx.x, b = blockIdx.y;
    int x0 = (bx >> 4) * 2, y0 = (bx & 15) * 2;
    int nch = Cin >> 5;
    int line = wid & 3;
    int cobase = (wid >> 2) * 64;
    int g = lane >> 2, t4 = lane & 3;

    // ldmatrix per-lane byte offsets (row pad 40 elems = 80B, conflict-free)
    uint32_t a_off = ((uint32_t)((lane & 7) + ((lane >> 3) & 1) * 8) * 40
                      + (uint32_t)(lane >> 4) * 8) * 2;
    uint32_t b_off = ((uint32_t)((lane & 7) + (lane >> 4) * 8) * 40
                      + (uint32_t)((lane >> 3) & 1) * 8) * 2;

    // W staging: 512 uint4 per plane; thread handles j and j+256
    int j0 = tid, j1 = tid + 256;
    uint32_t wd0 = (uint32_t)(j0 >> 2) * 80 + (uint32_t)(j0 & 3) * 16;
    uint32_t wd1 = (uint32_t)(j1 >> 2) * 80 + (uint32_t)(j1 & 3) * 16;

    float d[4][4][4];
    #pragma unroll
    for (int m = 0; m < 4; m++)
        #pragma unroll
        for (int n = 0; n < 4; n++)
            #pragma unroll
            for (int r = 0; r < 4; r++) d[m][n][r] = 0.f;

    for (int ch = 0; ch < nch; ch++) {
        __syncthreads();                 // previous chunk fully consumed
        if (tid < 16) flags[tid] = 0;
        __syncthreads();
        // zero z-halo rows (z_smem = 0 and 33)
        for (int i = tid; i < 1024; i += 256) {
            int ci = i & 31, r2 = (i >> 5) & 1, il = i >> 6;
            X[il * 1360 + (r2 ? 33 : 0) * 40 + ci] = __float2half_rn(0.f);
        }
        // stage X: 16 line tiles x 32 ci x 8 z-quads, set nonzero flags
        int c0 = ch * 32;
        for (int i = tid; i < 4096; i += 256) {
            int zq = i & 7, ci = (i >> 3) & 31, il = i >> 8;
            int gx = x0 - 1 + (il >> 2), gy = y0 - 1 + (il & 3);
            float4 v = make_float4(0.f, 0.f, 0.f, 0.f);
            if ((unsigned)gx < 32u && (unsigned)gy < 32u)
                v = *(const float4*)&in[(((size_t)(b * Cin + c0 + ci) * 32 + gx) * 32 + gy) * 32 + zq * 4];
            if (v.x != 0.f || v.y != 0.f || v.z != 0.f || v.w != 0.f) flags[il] = 1;
            int base = il * 1360 + (zq * 4 + 1) * 40 + ci;
            X[base]      = __float2half_rn(v.x);
            X[base + 40] = __float2half_rn(v.y);
            X[base + 80] = __float2half_rn(v.z);
            X[base + 120] = __float2half_rn(v.w);
        }
        // stage W[tap=0] into buf 0
        {
            const uint4* sh = (const uint4*)(wgt + (size_t)(0 * nch + ch) * 4096);
            *(uint4*)(smem + W_OFF + wd0) = sh[j0];
            *(uint4*)(smem + W_OFF + wd1) = sh[j1];
        }
        __syncthreads();

        for (int tap = 0; tap < 27; tap++) {
            int buf = tap & 1;
            uint4 nh0, nh1;
            bool pre = (tap < 26);
            if (pre) {   // register-prefetch next tap's W (overlaps MMAs)
                const uint4* sh = (const uint4*)(wgt + (size_t)((tap + 1) * nch + ch) * 4096);
                nh0 = sh[j0]; nh1 = sh[j1];
            }

            int dz = tap % 3, dyy = (tap / 3) % 3, dxx = tap / 9;
            int il = ((line >> 1) + dxx) * 4 + (line & 1) + dyy;
            if (flags[il]) {            // exact skip of all-zero input tiles
                uint32_t xb = x_u + (uint32_t)il * LSTRB + (uint32_t)dz * 80;
                uint32_t wb = w_u + (uint32_t)buf * WBUF + (uint32_t)cobase * 80;
                #pragma unroll
                for (int k = 0; k < 2; k++) {
                    uint32_t Bf[8];
                    ldsm4(&Bf[0], xb + (uint32_t)k * 32 + b_off);
                    ldsm4(&Bf[4], xb + 1280 + (uint32_t)k * 32 + b_off);
                    #pragma unroll
                    for (int m = 0; m < 4; m++) {
                        uint32_t Af[4];
                        ldsm4(Af, wb + (uint32_t)m * 1280 + (uint32_t)k * 32 + a_off);
                        #pragma unroll
                        for (int n = 0; n < 4; n++)
                            MMA_F16(d[m][n], Af[0], Af[1], Af[2], Af[3], Bf[n * 2], Bf[n * 2 + 1]);
                    }
                }
            }

            if (pre) {
                char* dst = smem + W_OFF + (buf ^ 1) * WBUF;
                *(uint4*)(dst + wd0) = nh0;
                *(uint4*)(dst + wd1) = nh1;
            }
            __syncthreads();
        }
    }

    // epilogue: write out + fused GroupNorm partial stats
    int ox = x0 + (line >> 1), oy = y0 + (line & 1);
    #pragma unroll
    for (int m = 0; m < 4; m++) {
        int co = cobase + m * 16 + g;
        float bv0 = bias[co], bv1 = bias[co + 8];
        float s = 0.f, s2 = 0.f;
        float* p0 = out + ((size_t)(b * COUT_ + co)) * R3_ + ox * 1024 + oy * 32;
        float* p1 = p0 + (size_t)8 * R3_;
        #pragma unroll
        for (int n = 0; n < 4; n++) {
            float v0 = d[m][n][0] + bv0, v1 = d[m][n][1] + bv0;
            float v2 = d[m][n][2] + bv1, v3 = d[m][n][3] + bv1;
            int z = n * 8 + t4 * 2;
            *(float2*)(p0 + z) = make_float2(v0, v1);
            *(float2*)(p1 + z) = make_float2(v2, v3);
            s += v0 + v1 + v2 + v3;
            s2 += v0 * v0 + v1 * v1 + v2 * v2 + v3 * v3;
        }
        #pragma unroll
        for (int off = 16; off > 0; off >>= 1) {
            s += __shfl_xor_sync(0xffffffffu, s, off);
            s2 += __shfl_xor_sync(0xffffffffu, s2, off);
        }
        if (lane == 0) {
            int grp = b * NG_ + (cobase >> 4) + m;
            atomicAdd(&gs[grp], s);
            atomicAdd(&gs2[grp], s2);
        }
    }
}

// ---------------- finalize GN stats (and reset accumulators) -----------------
__global__ void gn_finalize_kernel(float* __restrict__ gs, float* __restrict__ gs2,
                                   float* __restrict__ mean, float* __restrict__ rstd) {
    int i = threadIdx.x;            // 64 = B_*NG_
    const float n = 16.0f * (float)R3_;
    float s = gs[i], s2 = gs2[i];
    float m = s / n;
    mean[i] = m;
    rstd[i] = rsqrtf(s2 / n - m * m + GN_EPS_);
    gs[i] = 0.f; gs2[i] = 0.f;
}

__global__ void gn_apply_kernel(float* __restrict__ x, const float* __restrict__ gamma,
                                const float* __restrict__ beta,
                                const float* __restrict__ mean, const float* __restrict__ rstd,
                                int S) {
    int t = blockIdx.x * blockDim.x + threadIdx.x;
    int c = (t / S) % COUT_;
    int b = t / (S * COUT_);
    int idx = b * NG_ + (c >> 4);
    float y = (x[t] - mean[idx]) * rstd[idx] * gamma[c] + beta[c];
    x[t] = y / (1.0f + expf(-y));
}

// ---------------- GroupNorm stats (point branch only) ------------------------
__global__ void gn_stats_kernel(const float* __restrict__ x, int S,
                                float* __restrict__ mean, float* __restrict__ rstd) {
    int bg = blockIdx.x;
    const float* p = x + (long)bg * 16 * S;
    int n = 16 * S;
    float s = 0.f, s2 = 0.f;
    for (int i = threadIdx.x; i < n; i += blockDim.x) {
        float v = p[i];
        s += v; s2 += v * v;
    }
    __shared__ float ra[512], rb[512];
    int tid = threadIdx.x;
    ra[tid] = s; rb[tid] = s2; __syncthreads();
    for (int st = 256; st > 0; st >>= 1) {
        if (tid < st) { ra[tid] += ra[tid + st]; rb[tid] += rb[tid + st]; }
        __syncthreads();
    }
    if (tid == 0) {
        float m = ra[0] / (float)n;
        float var = rb[0] / (float)n - m * m;
        mean[bg] = m;
        rstd[bg] = rsqrtf(var + GN_EPS_);
    }
}

__global__ void ptgemm_kernel(const float* __restrict__ f, const float* __restrict__ w,
                              const float* __restrict__ bias, float* __restrict__ pf) {
    int t = blockIdx.x * blockDim.x + threadIdx.x;
    int n = t & (N_ - 1);
    int r = t >> 12;
    int o = (r & 31) * 4;
    int b = r >> 5;
    float a0 = bias[o], a1 = bias[o + 1], a2 = bias[o + 2], a3 = bias[o + 3];
    const float* fb = f + (b * CIN_) * N_ + n;
    const float* w0 = w + o * CIN_;
    #pragma unroll 8
    for (int c = 0; c < CIN_; c++) {
        float fv = fb[c * N_];
        a0 += w0[c] * fv;
        a1 += w0[CIN_ + c] * fv;
        a2 += w0[2 * CIN_ + c] * fv;
        a3 += w0[3 * CIN_ + c] * fv;
    }
    float* op = &pf[(b * COUT_ + o) * N_ + n];
    op[0] = a0; op[N_] = a1; op[2 * N_] = a2; op[3 * N_] = a3;
}

__global__ void final_kernel(const float* __restrict__ nc, const float* __restrict__ h2,
                             const float* __restrict__ pf, const float* __restrict__ gamma,
                             const float* __restrict__ beta,
                             const float* __restrict__ mean, const float* __restrict__ rstd,
                             float* __restrict__ out) {
    int t = blockIdx.x * blockDim.x + threadIdx.x;
    int n = t & (N_ - 1);
    int r = t >> 12;
    int o = (r & 31) * 4;
    int b = r >> 5;

    float ncx = nc[(b * N_ + n) * 3 + 0];
    float ncy = nc[(b * N_ + n) * 3 + 1];
    float ncz = nc[(b * N_ + n) * 3 + 2];
    float fx = floorf(ncx), fy = floorf(ncy), fz = floorf(ncz);
    float dx = ncx - fx, dy = ncy - fy, dz = ncz - fz;
    int ix0 = (int)fx, iy0 = (int)fy, iz0 = (int)fz;
    int ix1 = min(ix0 + 1, R_ - 1), iy1 = min(iy0 + 1, R_ - 1), iz1 = min(iz0 + 1, R_ - 1);
    float wx[2] = {1.f - dx, dx}, wy[2] = {1.f - dy, dy}, wz[2] = {1.f - dz, dz};
    int xs[2] = {ix0, ix1}, ys[2] = {iy0, iy1}, zs[2] = {iz0, iz1};

    float d0 = 0.f, d1 = 0.f, d2 = 0.f, d3 = 0.f;
    const float* hb = &h2[(b * COUT_ + o) * R3_];
    #pragma unroll
    for (int k = 0; k < 8; k++) {
        int kx = k >> 2, ky = (k >> 1) & 1, kz = k & 1;
        float wk = wx[kx] * wy[ky] * wz[kz];
        int id = (xs[kx] * R_ + ys[ky]) * R_ + zs[kz];
        d0 += wk * hb[id];
        d1 += wk * hb[R3_ + id];
        d2 += wk * hb[2 * R3_ + id];
        d3 += wk * hb[3 * R3_ + id];
    }

    int idx = b * NG_ + (o >> 4);
    float m = mean[idx], rs = rstd[idx];
    const float* pp = &pf[(b * COUT_ + o) * N_ + n];
    float* op = &out[(b * COUT_ + o) * N_ + n];
    float dv[4] = {d0, d1, d2, d3};
    #pragma unroll
    for (int j = 0; j < 4; j++) {
        int c = o + j;
        float y = (pp[j * N_] - m) * rs * gamma[c] + beta[c];
        op[j * N_] = dv[j] + y / (1.0f + expf(-y));
    }
}

// ---------------- host launcher ----------------------------------------------
extern "C" void kernel_launch(void* const* d_in, const int* in_sizes, int n_in,
                              void* d_out, int out_size) {
    const float* features = (const float*)d_in[0];
    const float* coords   = (const float*)d_in[1];
    const float* c1w = (const float*)d_in[2];
    const float* c1b = (const float*)d_in[3];
    const float* g1g = (const float*)d_in[4];
    const float* g1b = (const float*)d_in[5];
    const float* c2w = (const float*)d_in[6];
    const float* c2b = (const float*)d_in[7];
    const float* g2g = (const float*)d_in[8];
    const float* g2b = (const float*)d_in[9];
    const float* ptw = (const float*)d_in[10];
    const float* ptb = (const float*)d_in[11];
    const float* pgg = (const float*)d_in[12];
    const float* pgb = (const float*)d_in[13];
    float* out = (float*)d_out;

    float *grid_p, *cnt_p, *h1, *h2, *pf, *nc, *mean_p, *rstd_p, *gs, *gs2;
    int* vox_p;
    __half *w1, *w2;
    cudaGetSymbolAddress((void**)&grid_p, g_grid);
    cudaGetSymbolAddress((void**)&cnt_p, g_cnt);
    cudaGetSymbolAddress((void**)&vox_p, g_vox);
    cudaGetSymbolAddress((void**)&nc, g_nc);
    cudaGetSymbolAddress((void**)&h1, g_h1);
    cudaGetSymbolAddress((void**)&h2, g_h2);
    cudaGetSymbolAddress((void**)&pf, g_pf);
    cudaGetSymbolAddress((void**)&mean_p, g_mean);
    cudaGetSymbolAddress((void**)&rstd_p, g_rstd);
    cudaGetSymbolAddress((void**)&gs, g_sum);
    cudaGetSymbolAddress((void**)&gs2, g_sum2);
    cudaGetSymbolAddress((void**)&w1, g_w1);
    cudaGetSymbolAddress((void**)&w2, g_w2);

    cudaFuncSetAttribute(conv3d_mma_kernel,
                         cudaFuncAttributeMaxDynamicSharedMemorySize, CONV_SMEM);

    zero_kernel<<<4096, 256>>>(grid_p, cnt_p, gs, gs2);
    coords_kernel<<<B_, 256>>>(coords, nc, vox_p, cnt_p);
    scatter_kernel<<<8192, 256>>>(features, vox_p, grid_p);
    normgrid_kernel<<<65536, 256>>>(grid_p, cnt_p);
    wprep_kernel<<<(27 * 128 * CIN_ + 255) / 256, 256>>>(c1w, w1, CIN_);
    wprep_kernel<<<(27 * 128 * COUT_ + 255) / 256, 256>>>(c2w, w2, COUT_);

    conv3d_mma_kernel<<<dim3(256, 8), 256, CONV_SMEM>>>(grid_p, w1, c1b, h1, CIN_, gs, gs2);
    gn_finalize_kernel<<<1, B_ * NG_>>>(gs, gs2, mean_p, rstd_p);
    gn_apply_kernel<<<131072, 256>>>(h1, g1g, g1b, mean_p, rstd_p, R3_);

    conv3d_mma_kernel<<<dim3(256, 8), 256, CONV_SMEM>>>(h1, w2, c2b, h2, COUT_, gs, gs2);
    gn_finalize_kernel<<<1, B_ * NG_>>>(gs, gs2, mean_p, rstd_p);
    gn_apply_kernel<<<131072, 256>>>(h2, g2g, g2b, mean_p, rstd_p, R3_);

    ptgemm_kernel<<<4096, 256>>>(features, ptw, ptb, pf);
    gn_stats_kernel<<<B_ * NG_, 512>>>(pf, N_, mean_p, rstd_p);
    final_kernel<<<4096, 256>>>(nc, h2, pf, pgg, pgb, mean_p, rstd_p, out);
}

// round 8
// speedup vs baseline: 12.0517x; 1.0932x over previous
#include <cuda_runtime.h>
#include <cuda_fp16.h>
#include <math.h>
#include <stdint.h>

#define B_    8
#define N_    4096
#define CIN_  64
#define COUT_ 128
#define R_    32
#define R3_   32768
#define NG_   8
#define GN_EPS_ 1e-5f

// ---------------- scratch (static device globals; no allocation) -------------
static __device__ float g_grid[B_ * CIN_ * R3_];
static __device__ float g_cnt [B_ * R3_];
static __device__ int   g_vox [B_ * N_];
static __device__ float g_nc  [B_ * N_ * 3];
static __device__ float g_h1  [B_ * COUT_ * R3_];
static __device__ float g_h2  [B_ * COUT_ * R3_];
static __device__ float g_pf  [B_ * COUT_ * N_];
static __device__ float g_mean [B_ * NG_];
static __device__ float g_rstd [B_ * NG_];
static __device__ float g_mean2[B_ * NG_];
static __device__ float g_rstd2[B_ * NG_];
static __device__ float g_sum [B_ * NG_];
static __device__ float g_sum2[B_ * NG_];
// fp16 weights: [tap][ci-chunk32][co 128][ci 32]
static __device__ __half g_w1[27 * 2 * 128 * 32];
static __device__ __half g_w2[27 * 4 * 128 * 32];

// ---------------- mma.sync m16n8k16 fp16 ------------------------------------
#define MMA_F16(dd, a0, a1, a2, a3, b0, b1) \
    asm volatile("mma.sync.aligned.m16n8k16.row.col.f32.f16.f16.f32 " \
        "{%0,%1,%2,%3}, {%4,%5,%6,%7}, {%8,%9}, {%0,%1,%2,%3};" \
        : "+f"((dd)[0]), "+f"((dd)[1]), "+f"((dd)[2]), "+f"((dd)[3]) \
        : "r"(a0), "r"(a1), "r"(a2), "r"(a3), "r"(b0), "r"(b1))

__device__ __forceinline__ void ldsm4(uint32_t* r, uint32_t addr) {
    asm volatile("ldmatrix.sync.aligned.m8n8.x4.shared.b16 {%0,%1,%2,%3}, [%4];"
        : "=r"(r[0]), "=r"(r[1]), "=r"(r[2]), "=r"(r[3]) : "r"(addr));
}
__device__ __forceinline__ uint32_t smem_u32(const void* p) {
    uint32_t a;
    asm("{ .reg .u64 t; cvta.to.shared.u64 t, %1; cvt.u32.u64 %0, t; }" : "=r"(a) : "l"(p));
    return a;
}

// ============================ elementwise kernels ============================
__global__ void zero_kernel(float4* __restrict__ grid4, float4* __restrict__ cnt4,
                            float* __restrict__ gs, float* __restrict__ gs2) {
    int stride = gridDim.x * blockDim.x;
    int t0 = blockIdx.x * blockDim.x + threadIdx.x;
    const float4 z = make_float4(0.f, 0.f, 0.f, 0.f);
    for (int i = t0; i < (B_ * CIN_ * R3_) / 4; i += stride) grid4[i] = z;
    for (int i = t0; i < (B_ * R3_) / 4; i += stride) cnt4[i] = z;
    if (t0 < B_ * NG_) { gs[t0] = 0.f; gs2[t0] = 0.f; }
}

__global__ void coords_kernel(const float* __restrict__ coords,
                              float* __restrict__ nc, int* __restrict__ vox,
                              float* __restrict__ cnt) {
    int b = blockIdx.x, tid = threadIdx.x;
    __shared__ float red[256];
    __shared__ float smean[3];
    __shared__ float sinv;

    float s0 = 0.f, s1 = 0.f, s2 = 0.f;
    for (int n = tid; n < N_; n += 256) {
        const float* c = &coords[(b * N_ + n) * 3];
        s0 += c[0]; s1 += c[1]; s2 += c[2];
    }
    float ss[3] = {s0, s1, s2};
    for (int d = 0; d < 3; d++) {
        red[tid] = ss[d]; __syncthreads();
        for (int st = 128; st > 0; st >>= 1) {
            if (tid < st) red[tid] += red[tid + st];
            __syncthreads();
        }
        if (tid == 0) smean[d] = red[0] * (1.0f / N_);
        __syncthreads();
    }
    float m0 = smean[0], m1 = smean[1], m2 = smean[2];

    float mx = 0.f;
    for (int n = tid; n < N_; n += 256) {
        const float* c = &coords[(b * N_ + n) * 3];
        float dx = c[0] - m0, dy = c[1] - m1, dz = c[2] - m2;
        mx = fmaxf(mx, dx * dx + dy * dy + dz * dz);
    }
    red[tid] = mx; __syncthreads();
    for (int st = 128; st > 0; st >>= 1) {
        if (tid < st) red[tid] = fmaxf(red[tid], red[tid + st]);
        __syncthreads();
    }
    if (tid == 0) sinv = 1.0f / (2.0f * sqrtf(red[0]));
    __syncthreads();
    float inv = sinv;

    for (int n = tid; n < N_; n += 256) {
        const float* c = &coords[(b * N_ + n) * 3];
        float v[3]; int iv[3];
        float cc[3] = {c[0] - m0, c[1] - m1, c[2] - m2};
        #pragma unroll
        for (int d = 0; d < 3; d++) {
            float x = (cc[d] * inv + 0.5f) * (float)R_;
            x = fminf(fmaxf(x, 0.f), (float)(R_ - 1));
            v[d] = x;
            iv[d] = (int)rintf(x);
        }
        nc[(b * N_ + n) * 3 + 0] = v[0];
        nc[(b * N_ + n) * 3 + 1] = v[1];
        nc[(b * N_ + n) * 3 + 2] = v[2];
        int flat = (iv[0] * R_ + iv[1]) * R_ + iv[2];
        vox[b * N_ + n] = flat;
        atomicAdd(&cnt[b * R3_ + flat], 1.0f);
    }
}

__global__ void scatter_kernel(const float* __restrict__ f,
                               const int* __restrict__ vox,
                               float* __restrict__ grid) {
    int t = blockIdx.x * blockDim.x + threadIdx.x;
    int n = t & (N_ - 1);
    int bc = t >> 12;
    int b = bc >> 6;
    int flat = vox[b * N_ + n];
    atomicAdd(&grid[bc * R3_ + flat], f[t]);
}

// ---------------- weight prep (both convs, one launch): fp32 -> fp16 ---------
__global__ void wprep2_kernel(const float* __restrict__ w1, const float* __restrict__ w2,
                              __half* __restrict__ o1, __half* __restrict__ o2) {
    int t = blockIdx.x * 256 + threadIdx.x;
    const int N1 = 27 * 128 * CIN_;
    if (t < N1) {
        int ci = t % CIN_;
        int co = (t / CIN_) & 127;
        int tap = t / (CIN_ * 128);
        float v = w1[(co * CIN_ + ci) * 27 + tap];
        int idx = ((tap * (CIN_ >> 5) + (ci >> 5)) * 128 + co) * 32 + (ci & 31);
        o1[idx] = __float2half_rn(v);
    } else {
        t -= N1;
        if (t >= 27 * 128 * COUT_) return;
        int ci = t % COUT_;
        int co = (t / COUT_) & 127;
        int tap = t / (COUT_ * 128);
        float v = w2[(co * COUT_ + ci) * 27 + tap];
        int idx = ((tap * (COUT_ >> 5) + (ci >> 5)) * 128 + co) * 32 + (ci & 31);
        o2[idx] = __float2half_rn(v);
    }
}

// ============================ mma.sync conv3d (fp16) =========================
// CTA: 256 thr = 8 warps. Output tile: [128 co] x [2x2 xy lines x 32 z].
// SMEM: X [16 line tiles][34 z][40 pad] fp16 at 0 (43,520 B)
//       W double buffer [128][40] fp16 per buf at 43,520 (2 x 10,240 B)
//       flags[16] int at 64,000 ; rcnt[512] float at 64,064
#define LSTRB   2720
#define W_OFF   43520
#define WBUF    10240
#define FLG_OFF 64000
#define RC_OFF  64064
#define CONV_SMEM 66112

__global__ __launch_bounds__(256, 2)
void conv3d_mma_kernel(const float* __restrict__ in,
                       const __half* __restrict__ wgt,
                       const float* __restrict__ bias,
                       float* __restrict__ out, int Cin,
                       const float* __restrict__ cnt,   // non-null: normalize by count
                       float* __restrict__ gs, float* __restrict__ gs2) {
    extern __shared__ __align__(16) char smem[];
    __half* X = (__half*)smem;
    int* flags = (int*)(smem + FLG_OFF);
    float* rc = (float*)(smem + RC_OFF);
    uint32_t sb = smem_u32(smem);
    uint32_t x_u = sb, w_u = sb + W_OFF;

    int tid = threadIdx.x, wid = tid >> 5, lane = tid & 31;
    int bx = blockIdx.x, b = blockIdx.y;
    int x0 = (bx >> 4) * 2, y0 = (bx & 15) * 2;
    int nch = Cin >> 5;
    int line = wid & 3;
    int cobase = (wid >> 2) * 64;
    int g = lane >> 2, t4 = lane & 3;
    bool hc = (cnt != nullptr);

    uint32_t a_off = ((uint32_t)((lane & 7) + ((lane >> 3) & 1) * 8) * 40
                      + (uint32_t)(lane >> 4) * 8) * 2;
    uint32_t b_off = ((uint32_t)((lane & 7) + (lane >> 4) * 8) * 40
                      + (uint32_t)((lane >> 3) & 1) * 8) * 2;

    int j0 = tid, j1 = tid + 256;
    uint32_t wd0 = (uint32_t)(j0 >> 2) * 80 + (uint32_t)(j0 & 3) * 16;
    uint32_t wd1 = (uint32_t)(j1 >> 2) * 80 + (uint32_t)(j1 & 3) * 16;

    // once: flags + per-column reciprocal counts
    if (tid < 16) flags[tid] = hc ? 0 : 1;
    __syncthreads();
    if (hc) {
        for (int i = tid; i < 512; i += 256) {
            int il = i >> 5, z = i & 31;
            int gx = x0 - 1 + (il >> 2), gy = y0 - 1 + (il & 3);
            float c = 0.f;
            if ((unsigned)gx < 32u && (unsigned)gy < 32u)
                c = cnt[(size_t)b * R3_ + gx * 1024 + gy * 32 + z];
            rc[i] = __frcp_rn(fmaxf(c, 1.f));
            if (c > 0.f) flags[il] = 1;
        }
    }

    float d[4][4][4];
    #pragma unroll
    for (int m = 0; m < 4; m++)
        #pragma unroll
        for (int n = 0; n < 4; n++)
            #pragma unroll
            for (int r = 0; r < 4; r++) d[m][n][r] = 0.f;

    for (int ch = 0; ch < nch; ch++) {
        __syncthreads();                 // prev chunk fully consumed (+rcnt ready)
        for (int i = tid; i < 1024; i += 256) {
            int ci = i & 31, r2 = (i >> 5) & 1, il = i >> 6;
            X[il * 1360 + (r2 ? 33 : 0) * 40 + ci] = __float2half_rn(0.f);
        }
        int c0 = ch * 32;
        for (int i = tid; i < 4096; i += 256) {
            int zq = i & 7, ci = (i >> 3) & 31, il = i >> 8;
            int gx = x0 - 1 + (il >> 2), gy = y0 - 1 + (il & 3);
            float4 v = make_float4(0.f, 0.f, 0.f, 0.f);
            if ((unsigned)gx < 32u && (unsigned)gy < 32u)
                v = *(const float4*)&in[(((size_t)(b * Cin + c0 + ci) * 32 + gx) * 32 + gy) * 32 + zq * 4];
            if (hc) {
                const float* r4 = &rc[il * 32 + zq * 4];
                v.x *= r4[0]; v.y *= r4[1]; v.z *= r4[2]; v.w *= r4[3];
            }
            int base = il * 1360 + (zq * 4 + 1) * 40 + ci;
            X[base]       = __float2half_rn(v.x);
            X[base + 40]  = __float2half_rn(v.y);
            X[base + 80]  = __float2half_rn(v.z);
            X[base + 120] = __float2half_rn(v.w);
        }
        {
            const uint4* sh = (const uint4*)(wgt + (size_t)(0 * nch + ch) * 4096);
            *(uint4*)(smem + W_OFF + wd0) = sh[j0];
            *(uint4*)(smem + W_OFF + wd1) = sh[j1];
        }
        __syncthreads();

        for (int tap = 0; tap < 27; tap++) {
            int buf = tap & 1;
            uint4 nh0, nh1;
            bool pre = (tap < 26);
            if (pre) {
                const uint4* sh = (const uint4*)(wgt + (size_t)((tap + 1) * nch + ch) * 4096);
                nh0 = sh[j0]; nh1 = sh[j1];
            }

            int dz = tap % 3, dyy = (tap / 3) % 3, dxx = tap / 9;
            int il = ((line >> 1) + dxx) * 4 + (line & 1) + dyy;
            if (flags[il]) {
                uint32_t xb = x_u + (uint32_t)il * LSTRB + (uint32_t)dz * 80;
                uint32_t wb = w_u + (uint32_t)buf * WBUF + (uint32_t)cobase * 80;
                #pragma unroll
                for (int k = 0; k < 2; k++) {
                    uint32_t Bf[8];
                    ldsm4(&Bf[0], xb + (uint32_t)k * 32 + b_off);
                    ldsm4(&Bf[4], xb + 1280 + (uint32_t)k * 32 + b_off);
                    #pragma unroll
                    for (int m = 0; m < 4; m++) {
                        uint32_t Af[4];
                        ldsm4(Af, wb + (uint32_t)m * 1280 + (uint32_t)k * 32 + a_off);
                        #pragma unroll
                        for (int n = 0; n < 4; n++)
                            MMA_F16(d[m][n], Af[0], Af[1], Af[2], Af[3], Bf[n * 2], Bf[n * 2 + 1]);
                    }
                }
            }

            if (pre) {
                char* dst = smem + W_OFF + (buf ^ 1) * WBUF;
                *(uint4*)(dst + wd0) = nh0;
                *(uint4*)(dst + wd1) = nh1;
            }
            __syncthreads();
        }
    }

    // epilogue: write out + fused GroupNorm partial stats
    int ox = x0 + (line >> 1), oy = y0 + (line & 1);
    #pragma unroll
    for (int m = 0; m < 4; m++) {
        int co = cobase + m * 16 + g;
        float bv0 = bias[co], bv1 = bias[co + 8];
        float s = 0.f, s2 = 0.f;
        float* p0 = out + ((size_t)(b * COUT_ + co)) * R3_ + ox * 1024 + oy * 32;
        float* p1 = p0 + (size_t)8 * R3_;
        #pragma unroll
        for (int n = 0; n < 4; n++) {
            float v0 = d[m][n][0] + bv0, v1 = d[m][n][1] + bv0;
            float v2 = d[m][n][2] + bv1, v3 = d[m][n][3] + bv1;
            int z = n * 8 + t4 * 2;
            *(float2*)(p0 + z) = make_float2(v0, v1);
            *(float2*)(p1 + z) = make_float2(v2, v3);
            s += v0 + v1 + v2 + v3;
            s2 += v0 * v0 + v1 * v1 + v2 * v2 + v3 * v3;
        }
        #pragma unroll
        for (int off = 16; off > 0; off >>= 1) {
            s += __shfl_xor_sync(0xffffffffu, s, off);
            s2 += __shfl_xor_sync(0xffffffffu, s2, off);
        }
        if (lane == 0) {
            int grp = b * NG_ + (cobase >> 4) + m;
            atomicAdd(&gs[grp], s);
            atomicAdd(&gs2[grp], s2);
        }
    }
}

// ---------------- finalize GN stats (and reset accumulators) -----------------
__global__ void gn_finalize_kernel(float* __restrict__ gs, float* __restrict__ gs2,
                                   float* __restrict__ mean, float* __restrict__ rstd) {
    int i = threadIdx.x;            // 64 = B_*NG_
    const float n = 16.0f * (float)R3_;
    float s = gs[i], s2 = gs2[i];
    float m = s / n;
    mean[i] = m;
    rstd[i] = rsqrtf(s2 / n - m * m + GN_EPS_);
    gs[i] = 0.f; gs2[i] = 0.f;
}

__global__ void gn_apply_kernel(float* __restrict__ x, const float* __restrict__ gamma,
                                const float* __restrict__ beta,
                                const float* __restrict__ mean, const float* __restrict__ rstd,
                                int S) {
    int t = blockIdx.x * blockDim.x + threadIdx.x;
    int c = (t / S) % COUT_;
    int b = t / (S * COUT_);
    int idx = b * NG_ + (c >> 4);
    float y = (x[t] - mean[idx]) * rstd[idx] * gamma[c] + beta[c];
    x[t] = y / (1.0f + expf(-y));
}

// ---------------- GroupNorm stats (point branch) -----------------------------
__global__ void gn_stats_kernel(const float* __restrict__ x, int S,
                                float* __restrict__ mean, float* __restrict__ rstd) {
    int bg = blockIdx.x;
    const float* p = x + (long)bg * 16 * S;
    int n = 16 * S;
    float s = 0.f, s2 = 0.f;
    for (int i = threadIdx.x; i < n; i += blockDim.x) {
        float v = p[i];
        s += v; s2 += v * v;
    }
    __shared__ float ra[512], rb[512];
    int tid = threadIdx.x;
    ra[tid] = s; rb[tid] = s2; __syncthreads();
    for (int st = 256; st > 0; st >>= 1) {
        if (tid < st) { ra[tid] += ra[tid + st]; rb[tid] += rb[tid + st]; }
        __syncthreads();
    }
    if (tid == 0) {
        float m = ra[0] / (float)n;
        float var = rb[0] / (float)n - m * m;
        mean[bg] = m;
        rstd[bg] = rsqrtf(var + GN_EPS_);
    }
}

__global__ void ptgemm_kernel(const float* __restrict__ f, const float* __restrict__ w,
                              const float* __restrict__ bias, float* __restrict__ pf) {
    int t = blockIdx.x * blockDim.x + threadIdx.x;
    int n = t & (N_ - 1);
    int r = t >> 12;
    int o = (r & 31) * 4;
    int b = r >> 5;
    float a0 = bias[o], a1 = bias[o + 1], a2 = bias[o + 2], a3 = bias[o + 3];
    const float* fb = f + (b * CIN_) * N_ + n;
    const float* w0 = w + o * CIN_;
    #pragma unroll 8
    for (int c = 0; c < CIN_; c++) {
        float fv = fb[c * N_];
        a0 += w0[c] * fv;
        a1 += w0[CIN_ + c] * fv;
        a2 += w0[2 * CIN_ + c] * fv;
        a3 += w0[3 * CIN_ + c] * fv;
    }
    float* op = &pf[(b * COUT_ + o) * N_ + n];
    op[0] = a0; op[N_] = a1; op[2 * N_] = a2; op[3 * N_] = a3;
}

// -------- devoxelize with fused GN+swish(h2) + point-branch GN/swish + add ---
__global__ void final_kernel(const float* __restrict__ nc, const float* __restrict__ h2,
                             const float* __restrict__ pf,
                             const float* __restrict__ g2g, const float* __restrict__ g2b,
                             const float* __restrict__ mean2, const float* __restrict__ rstd2,
                             const float* __restrict__ pgg, const float* __restrict__ pgb,
                             const float* __restrict__ meanp, const float* __restrict__ rstdp,
                             float* __restrict__ out) {
    int t = blockIdx.x * blockDim.x + threadIdx.x;
    int n = t & (N_ - 1);
    int r = t >> 12;
    int o = (r & 31) * 4;
    int b = r >> 5;

    float ncx = nc[(b * N_ + n) * 3 + 0];
    float ncy = nc[(b * N_ + n) * 3 + 1];
    float ncz = nc[(b * N_ + n) * 3 + 2];
    float fx = floorf(ncx), fy = floorf(ncy), fz = floorf(ncz);
    float dx = ncx - fx, dy = ncy - fy, dz = ncz - fz;
    int ix0 = (int)fx, iy0 = (int)fy, iz0 = (int)fz;
    int ix1 = min(ix0 + 1, R_ - 1), iy1 = min(iy0 + 1, R_ - 1), iz1 = min(iz0 + 1, R_ - 1);
    float wx[2] = {1.f - dx, dx}, wy[2] = {1.f - dy, dy}, wz[2] = {1.f - dz, dz};
    int xs[2] = {ix0, ix1}, ys[2] = {iy0, iy1}, zs[2] = {iz0, iz1};

    int gidx = b * NG_ + (o >> 4);
    float m2 = mean2[gidx], rs2 = rstd2[gidx];
    float ga[4], be[4];
    #pragma unroll
    for (int j = 0; j < 4; j++) { ga[j] = g2g[o + j]; be[j] = g2b[o + j]; }

    float dv[4] = {0.f, 0.f, 0.f, 0.f};
    const float* hb = &h2[(size_t)(b * COUT_ + o) * R3_];
    #pragma unroll
    for (int k = 0; k < 8; k++) {
        int kx = k >> 2, ky = (k >> 1) & 1, kz = k & 1;
        float wk = wx[kx] * wy[ky] * wz[kz];
        int id = (xs[kx] * R_ + ys[ky]) * R_ + zs[kz];
        #pragma unroll
        for (int j = 0; j < 4; j++) {
            float y = (hb[(size_t)j * R3_ + id] - m2) * rs2 * ga[j] + be[j];
            dv[j] += wk * (y / (1.0f + expf(-y)));
        }
    }

    float mp = meanp[gidx], rsp = rstdp[gidx];
    const float* pp = &pf[(b * COUT_ + o) * N_ + n];
    float* op = &out[(b * COUT_ + o) * N_ + n];
    #pragma unroll
    for (int j = 0; j < 4; j++) {
        int c = o + j;
        float y = (pp[j * N_] - mp) * rsp * pgg[c] + pgb[c];
        op[j * N_] = dv[j] + y / (1.0f + expf(-y));
    }
}

// ---------------- host launcher ----------------------------------------------
extern "C" void kernel_launch(void* const* d_in, const int* in_sizes, int n_in,
                              void* d_out, int out_size) {
    const float* features = (const float*)d_in[0];
    const float* coords   = (const float*)d_in[1];
    const float* c1w = (const float*)d_in[2];
    const float* c1b = (const float*)d_in[3];
    const float* g1g = (const float*)d_in[4];
    const float* g1b = (const float*)d_in[5];
    const float* c2w = (const float*)d_in[6];
    const float* c2b = (const float*)d_in[7];
    const float* g2g = (const float*)d_in[8];
    const float* g2b = (const float*)d_in[9];
    const float* ptw = (const float*)d_in[10];
    const float* ptb = (const float*)d_in[11];
    const float* pgg = (const float*)d_in[12];
    const float* pgb = (const float*)d_in[13];
    float* out = (float*)d_out;

    float *grid_p, *cnt_p, *h1, *h2, *pf, *nc;
    float *mean_p, *rstd_p, *mean2_p, *rstd2_p, *gs, *gs2;
    int* vox_p;
    __half *w1, *w2;
    cudaGetSymbolAddress((void**)&grid_p, g_grid);
    cudaGetSymbolAddress((void**)&cnt_p, g_cnt);
    cudaGetSymbolAddress((void**)&vox_p, g_vox);
    cudaGetSymbolAddress((void**)&nc, g_nc);
    cudaGetSymbolAddress((void**)&h1, g_h1);
    cudaGetSymbolAddress((void**)&h2, g_h2);
    cudaGetSymbolAddress((void**)&pf, g_pf);
    cudaGetSymbolAddress((void**)&mean_p, g_mean);
    cudaGetSymbolAddress((void**)&rstd_p, g_rstd);
    cudaGetSymbolAddress((void**)&mean2_p, g_mean2);
    cudaGetSymbolAddress((void**)&rstd2_p, g_rstd2);
    cudaGetSymbolAddress((void**)&gs, g_sum);
    cudaGetSymbolAddress((void**)&gs2, g_sum2);
    cudaGetSymbolAddress((void**)&w1, g_w1);
    cudaGetSymbolAddress((void**)&w2, g_w2);

    cudaFuncSetAttribute(conv3d_mma_kernel,
                         cudaFuncAttributeMaxDynamicSharedMemorySize, CONV_SMEM);

    // launch order matters: conv1 is launch #6 so ncu (-s 5 -c 1) profiles it
    zero_kernel<<<4096, 256>>>((float4*)grid_p, (float4*)cnt_p, gs, gs2);            // 1
    coords_kernel<<<B_, 256>>>(coords, nc, vox_p, cnt_p);                            // 2
    scatter_kernel<<<8192, 256>>>(features, vox_p, grid_p);                          // 3
    wprep2_kernel<<<(27 * 128 * (CIN_ + COUT_) + 255) / 256, 256>>>(c1w, c2w, w1, w2); // 4
    ptgemm_kernel<<<4096, 256>>>(features, ptw, ptb, pf);                            // 5
    conv3d_mma_kernel<<<dim3(256, 8), 256, CONV_SMEM>>>(grid_p, w1, c1b, h1, CIN_,
                                                        cnt_p, gs, gs2);             // 6
    gn_finalize_kernel<<<1, B_ * NG_>>>(gs, gs2, mean_p, rstd_p);                    // 7
    gn_apply_kernel<<<131072, 256>>>(h1, g1g, g1b, mean_p, rstd_p, R3_);             // 8
    conv3d_mma_kernel<<<dim3(256, 8), 256, CONV_SMEM>>>(h1, w2, c2b, h2, COUT_,
                                                        nullptr, gs, gs2);           // 9
    gn_finalize_kernel<<<1, B_ * NG_>>>(gs, gs2, mean2_p, rstd2_p);                  // 10
    gn_stats_kernel<<<B_ * NG_, 512>>>(pf, N_, mean_p, rstd_p);                      // 11
    final_kernel<<<4096, 256>>>(nc, h2, pf, g2g, g2b, mean2_p, rstd2_p,
                                pgg, pgb, mean_p, rstd_p, out);                      // 12
}